// round 14
// baseline (speedup 1.0000x reference)
#include <cuda_runtime.h>
#include <cuda_fp16.h>
#include <math.h>
#include <stdint.h>

// ---------------- problem constants ----------------
#define NLAYERS 4
#define DMODEL  512
#define NHEAD   8
#define HDIM    64
#define DFF     2048
#define BATCH   8
#define SEQ     1024
#define MROWS   (BATCH*SEQ)
#define LN_EPS  1e-3f
#define QKVN    1536

#define WLAYER  3145728
#define WT_ELEMS (NLAYERS*WLAYER)

// ---------------- device scratch ----------------
__device__ float g_x   [MROWS*DMODEL];
__device__ __half g_qkvh[MROWS*QKVN];
__device__ __half g_lnh[MROWS*DMODEL];
__device__ __half g_pah[MROWS*DMODEL];
__device__ __half g_pfh[MROWS*DFF];
__device__ uint4 g_wth [WT_ELEMS/8];     // weights fp16, [N][K] transposed

extern __shared__ char dyn_smem[];

// ---------------- helpers ----------------
__device__ __forceinline__ void mma16816h(float* c, const uint32_t* a, uint32_t b0, uint32_t b1) {
    asm volatile(
        "mma.sync.aligned.m16n8k16.row.col.f32.f16.f16.f32 "
        "{%0,%1,%2,%3}, {%4,%5,%6,%7}, {%8,%9}, {%0,%1,%2,%3};"
        : "+f"(c[0]), "+f"(c[1]), "+f"(c[2]), "+f"(c[3])
        : "r"(a[0]), "r"(a[1]), "r"(a[2]), "r"(a[3]), "r"(b0), "r"(b1));
}
#define LDSM4(r0, r1, r2, r3, addr) \
    asm volatile("ldmatrix.sync.aligned.m8n8.x4.shared.b16 {%0,%1,%2,%3}, [%4];" \
        : "=r"(r0), "=r"(r1), "=r"(r2), "=r"(r3) : "r"(addr))

__device__ __forceinline__ void cpasync16(uint32_t saddr, const void* gptr) {
    asm volatile("cp.async.cg.shared.global [%0], [%1], 16;" :: "r"(saddr), "l"(gptr));
}
__device__ __forceinline__ uint32_t smem_u32(const void* p) {
    uint32_t a;
    asm("{ .reg .u64 t; cvta.to.shared.u64 t, %1; cvt.u32.u64 %0, t; }" : "=r"(a) : "l"(p));
    return a;
}
__device__ __forceinline__ void cp_commit() { asm volatile("cp.async.commit_group;" ::: "memory"); }
__device__ __forceinline__ void cp_wait1()  { asm volatile("cp.async.wait_group 1;"  ::: "memory"); }

__device__ __forceinline__ uint32_t ph2(float x, float y) {
    __half2 h = __floats2half2_rn(x, y);
    return *(uint32_t*)&h;
}
__device__ __forceinline__ uint32_t prmt(uint32_t a, uint32_t b, uint32_t s) {
    uint32_t d;
    asm("prmt.b32 %0, %1, %2, %3;" : "=r"(d) : "r"(a), "r"(b), "r"(s));
    return d;
}

// ---------------- positional encoding ----------------
__global__ void posenc_kernel(const float* __restrict__ x, float* __restrict__ out) {
    int idx = blockIdx.x * 256 + threadIdx.x;
    if (idx >= MROWS * DMODEL) return;
    int d = idx & (DMODEL - 1);
    int s = (idx / DMODEL) & (SEQ - 1);
    const int half = DMODEL / 2;
    float val;
    if (d < half) {
        float ang = (float)s * expf(-logf(10000.0f) * (2.0f * (float)d / (float)DMODEL));
        val = sinf(ang);
    } else {
        float j = (float)(d - half);
        float ang = (float)s * expf(-logf(10000.0f) * (2.0f * j / (float)DMODEL));
        val = cosf(ang);
    }
    out[idx] = x[idx] + val;
}

// ---------------- layernorm -> fp16 ----------------
__global__ void ln_kernel(const float* __restrict__ x, const float* __restrict__ gamma,
                          const float* __restrict__ beta, __half* __restrict__ oh) {
    int row = blockIdx.x;
    int t = threadIdx.x;
    const float4* xr = (const float4*)(x + (size_t)row * DMODEL);
    float4 v = xr[t];

    __shared__ float red1[4];
    __shared__ float red2[4];

    float s = v.x + v.y + v.z + v.w;
    #pragma unroll
    for (int o = 16; o > 0; o >>= 1) s += __shfl_xor_sync(0xffffffffu, s, o);
    if ((t & 31) == 0) red1[t >> 5] = s;
    __syncthreads();
    float mean = (red1[0] + red1[1] + red1[2] + red1[3]) * (1.0f / DMODEL);

    float dx = v.x - mean, dy = v.y - mean, dz = v.z - mean, dw = v.w - mean;
    float s2 = dx*dx + dy*dy + dz*dz + dw*dw;
    #pragma unroll
    for (int o = 16; o > 0; o >>= 1) s2 += __shfl_xor_sync(0xffffffffu, s2, o);
    if ((t & 31) == 0) red2[t >> 5] = s2;
    __syncthreads();
    float var = (red2[0] + red2[1] + red2[2] + red2[3]) * (1.0f / DMODEL);
    float rs = rsqrtf(var + LN_EPS);

    float4 g4 = ((const float4*)gamma)[t];
    float4 b4 = ((const float4*)beta)[t];
    float o0 = dx * rs * g4.x + b4.x;
    float o1 = dy * rs * g4.y + b4.y;
    float o2 = dz * rs * g4.z + b4.z;
    float o3 = dw * rs * g4.w + b4.w;
    *(uint2*)(oh + (size_t)row * DMODEL + t * 4) =
        make_uint2(ph2(o0, o1), ph2(o2, o3));
}

// ---------------- fused weight convert+transpose: ALL 24 matrices, one launch ----------------
#define WCONV_BLOCKS (NLAYERS * 3072)

__global__ void wconv_all(const float* __restrict__ Wq, const float* __restrict__ Wk,
                          const float* __restrict__ Wv, const float* __restrict__ Wo,
                          const float* __restrict__ W1, const float* __restrict__ W2,
                          __half* __restrict__ Oh) {
    __shared__ float tile[32][33];
    int bid = blockIdx.x;
    int l = bid / 3072;
    int r = bid - l * 3072;

    const float* src;
    size_t dstoff;
    int K, N, tx, ty;
    if (r < 1024) {
        int mat = r >> 8;
        int t = r & 255;
        K = 512; N = 512;
        src = (mat == 0 ? Wq : mat == 1 ? Wk : mat == 2 ? Wv : Wo) + (size_t)l * 262144;
        dstoff = (size_t)l * WLAYER + (size_t)mat * 262144;
        tx = t & 15; ty = t >> 4;
    } else if (r < 2048) {
        int t = r - 1024;
        K = 512; N = 2048;
        src = W1 + (size_t)l * 1048576;
        dstoff = (size_t)l * WLAYER + 1048576;
        tx = t & 63; ty = t >> 6;
    } else {
        int t = r - 2048;
        K = 2048; N = 512;
        src = W2 + (size_t)l * 1048576;
        dstoff = (size_t)l * WLAYER + 2097152;
        tx = t & 15; ty = t >> 4;
    }

    int tn = tx * 32, tk = ty * 32;
    int x = threadIdx.x, y = threadIdx.y;     // (32, 8)
    #pragma unroll
    for (int i = 0; i < 4; i++)
        tile[y + i * 8][x] = src[(size_t)(tk + y + i * 8) * N + tn + x];
    __syncthreads();
    __half* dst = Oh + dstoff;
    #pragma unroll
    for (int i = 0; i < 4; i++) {
        int nl = y + i * 8;
        dst[(size_t)(tn + nl) * K + tk + x] = __float2half_rn(tile[x][nl]);
    }
}

// ---------------- 3-stage BK=64 pipelined fp16 mma GEMM with ldmatrix, 128x128 tile ----------------
#define BKW 36                                 // u32 row stride (144 B) — conflict-free for ldmatrix
#define ARRB (128 * BKW * 4)                   // bytes per operand array = 18432
#define STAGE_BYTES (2 * ARRB)                 // 36864 (A + B)
#define GEMM_SMEM3 (3 * STAGE_BYTES)           // 110592

template<int EPI, int OUTF32, int OUTF16>
__global__ __launch_bounds__(256, 2) void gemm_pipe(
    const __half* __restrict__ Ah,
    const __half* __restrict__ Wh,
    const float* __restrict__ bias, const float* __restrict__ res,
    float* __restrict__ Cf, __half* __restrict__ Ch,
    int K, int N)
{
    uint32_t sbase = smem_u32(dyn_smem);
    int tid = threadIdx.x;
    int lane = tid & 31, wid = tid >> 5;
    int wm = wid >> 1, wn = wid & 1;
    int m0 = blockIdx.y * 128, n0 = blockIdx.x * 128;
    int g = lane >> 2, t = lane & 3;

    int lrow = tid >> 1;
    int lhalf = tid & 1;

    const __half* agh = Ah + (size_t)(m0 + lrow) * K;
    const __half* bgh = Wh + (size_t)(n0 + lrow) * K;
    uint32_t srow = sbase + (uint32_t)(lrow * BKW) * 4;

    uint32_t a_lane = sbase + (uint32_t)((wm * 32 + (lane & 15)) * BKW) * 4 + (uint32_t)(lane >> 4) * 16;
    uint32_t b_lane = sbase + (uint32_t)ARRB
                    + (uint32_t)((wn * 64 + (lane >> 4) * 8 + (lane & 7)) * BKW) * 4
                    + (uint32_t)((lane >> 3) & 1) * 16;

    const int nkb = K >> 6;

    auto issue_load = [&](int k, int st) {
        if (k < nkb) {
            int kb = k << 6;
            uint32_t so = srow + (uint32_t)st * STAGE_BYTES;
            #pragma unroll
            for (int p = 0; p < 4; p++) {
                int q = lhalf * 4 + p;              // 16B chunk 0..7 (64 halves/row)
                int ge = kb + q * 8;
                uint32_t sb2 = so + (uint32_t)(q * 16);
                cpasync16(sb2,        agh + ge);
                cpasync16(sb2 + ARRB, bgh + ge);
            }
        }
        cp_commit();
    };

    float c[2][8][4];
    #pragma unroll
    for (int mt = 0; mt < 2; mt++)
        #pragma unroll
        for (int nt = 0; nt < 8; nt++)
            #pragma unroll
            for (int e = 0; e < 4; e++) c[mt][nt][e] = 0.0f;

    issue_load(0, 0);
    issue_load(1, 1);
    int ls = 2;   // stage for next load (k+2)
    int cs = 0;   // stage to compute

    for (int k = 0; k < nkb; k++) {
        cp_wait1();                 // groups <= k complete (k+1 may be in flight)
        __syncthreads();            // all warps finished compute k-1 -> stage ls reusable
        issue_load(k + 2, ls);
        ls = (ls == 2) ? 0 : ls + 1;

        uint32_t so = (uint32_t)cs * STAGE_BYTES;
        cs = (cs == 2) ? 0 : cs + 1;
        uint32_t abase = a_lane + so;
        uint32_t bbase = b_lane + so;

        #pragma unroll
        for (int s = 0; s < 4; s++) {
            uint32_t acol = (uint32_t)(s * 32);      // 16 halves per k16 step
            uint32_t a0[4], a1[4];
            LDSM4(a0[0], a0[1], a0[2], a0[3], abase + acol);
            LDSM4(a1[0], a1[1], a1[2], a1[3], abase + acol + 16 * BKW * 4);
            #pragma unroll
            for (int p = 0; p < 4; p++) {
                uint32_t b0, b1, b2, b3;
                LDSM4(b0, b1, b2, b3, bbase + acol + (uint32_t)(p * 16 * BKW * 4));
                mma16816h(c[0][2 * p],     a0, b0, b1);
                mma16816h(c[1][2 * p],     a1, b0, b1);
                mma16816h(c[0][2 * p + 1], a0, b2, b3);
                mma16816h(c[1][2 * p + 1], a1, b2, b3);
            }
        }
    }

    #pragma unroll
    for (int mt = 0; mt < 2; mt++) {
        #pragma unroll
        for (int nt = 0; nt < 8; nt++) {
            int row = m0 + wm * 32 + mt * 16 + g;
            int col = n0 + wn * 64 + nt * 8 + t * 2;
            float2 v1 = make_float2(c[mt][nt][0], c[mt][nt][1]);
            float2 v2 = make_float2(c[mt][nt][2], c[mt][nt][3]);
            if (EPI == 2 || EPI == 3) {
                float2 bb = *(const float2*)(bias + col);
                v1.x += bb.x; v1.y += bb.y;
                v2.x += bb.x; v2.y += bb.y;
            }
            if (EPI == 2) {
                v1.x = fmaxf(v1.x, 0.0f); v1.y = fmaxf(v1.y, 0.0f);
                v2.x = fmaxf(v2.x, 0.0f); v2.y = fmaxf(v2.y, 0.0f);
            }
            if (EPI == 1 || EPI == 3) {
                float2 r1 = *(const float2*)(res + (size_t)row * N + col);
                float2 r2 = *(const float2*)(res + (size_t)(row + 8) * N + col);
                v1.x += r1.x; v1.y += r1.y;
                v2.x += r2.x; v2.y += r2.y;
            }
            if (OUTF32) {
                *(float2*)(Cf + (size_t)row * N + col) = v1;
                *(float2*)(Cf + (size_t)(row + 8) * N + col) = v2;
            }
            if (OUTF16) {
                *(uint32_t*)(Ch + (size_t)row * N + col) = ph2(v1.x, v1.y);
                *(uint32_t*)(Ch + (size_t)(row + 8) * N + col) = ph2(v2.x, v2.y);
            }
        }
    }
}

// ---------------- tensor-core flash attention (fp16 in/out) ----------------
#define AQP 36
#define ATT_SMEM (((128 + 64 + 64) * AQP) * 4 + 256)

__global__ __launch_bounds__(256) void attn_mma(
    const __half* __restrict__ qkv, const int* __restrict__ mask,
    __half* __restrict__ oh)
{
    uint32_t* Qs = (uint32_t*)dyn_smem;
    uint32_t* Ks = Qs + 128 * AQP;
    uint32_t* Vt = Ks + 64 * AQP;
    float* mb = (float*)(Vt + 64 * AQP);

    int tid = threadIdx.x;
    int lane = tid & 31, wid = tid >> 5;
    int g = lane >> 2, t = lane & 3;
    int b = blockIdx.y >> 3, h = blockIdx.y & 7;
    int q0 = blockIdx.x * 128;
    const float scale = 0.125f;

    #pragma unroll
    for (int p = 0; p < 8; p++) {
        int idx = tid + p * 256;
        int row = idx >> 4, c4 = (idx & 15) * 4;
        uint2 f = *(const uint2*)(qkv + (size_t)(b * SEQ + q0 + row) * QKVN + h * HDIM + c4);
        Qs[row * AQP + c4 / 2]     = f.x;
        Qs[row * AQP + c4 / 2 + 1] = f.y;
    }

    float m2[2] = {-INFINITY, -INFINITY};
    float l2[2] = {0.0f, 0.0f};
    float o[8][4];
    #pragma unroll
    for (int nt = 0; nt < 8; nt++)
        #pragma unroll
        for (int e = 0; e < 4; e++) o[nt][e] = 0.0f;

    int qrow = wid * 16;

    for (int kt = 0; kt < SEQ / 64; kt++) {
        __syncthreads();
        #pragma unroll
        for (int p = 0; p < 4; p++) {
            int idx = tid + p * 256;
            int row = idx >> 4, c4 = (idx & 15) * 4;
            uint2 f = *(const uint2*)(qkv + (size_t)(b * SEQ + kt * 64 + row) * QKVN + DMODEL + h * HDIM + c4);
            Ks[row * AQP + c4 / 2]     = f.x;
            Ks[row * AQP + c4 / 2 + 1] = f.y;
        }
        #pragma unroll
        for (int it = 0; it < 2; it++) {
            int hd0 = ((tid >> 5) + it * 8) * 4;
            int kp = tid & 31;
            const __half* v0 = qkv + (size_t)(b * SEQ + kt * 64 + kp * 2) * QKVN + 2 * DMODEL + h * HDIM + hd0;
            uint2 fa = *(const uint2*)v0;
            uint2 fb = *(const uint2*)(v0 + QKVN);
            Vt[(hd0 + 0) * AQP + kp] = prmt(fa.x, fb.x, 0x5410);
            Vt[(hd0 + 1) * AQP + kp] = prmt(fa.x, fb.x, 0x7632);
            Vt[(hd0 + 2) * AQP + kp] = prmt(fa.y, fb.y, 0x5410);
            Vt[(hd0 + 3) * AQP + kp] = prmt(fa.y, fb.y, 0x7632);
        }
        if (tid < 64)
            mb[tid] = (mask[b * SEQ + kt * 64 + tid] != 0) ? 0.0f : -1e9f;
        __syncthreads();

        float sv[8][4];
        #pragma unroll
        for (int nt = 0; nt < 8; nt++)
            #pragma unroll
            for (int e = 0; e < 4; e++) sv[nt][e] = 0.0f;

        #pragma unroll
        for (int s = 0; s < 4; s++) {
            uint32_t a[4];
            int ab = (qrow + g) * AQP + s * 8 + t;
            a[0] = Qs[ab];
            a[1] = Qs[ab + 8 * AQP];
            a[2] = Qs[ab + 4];
            a[3] = Qs[ab + 8 * AQP + 4];
            #pragma unroll
            for (int nt = 0; nt < 8; nt++) {
                int bb = (nt * 8 + g) * AQP + s * 8 + t;
                mma16816h(sv[nt], a, Ks[bb], Ks[bb + 4]);
            }
        }

        float rm0 = -INFINITY, rm1 = -INFINITY;
        #pragma unroll
        for (int nt = 0; nt < 8; nt++) {
            int col = nt * 8 + t * 2;
            float mb0 = mb[col], mb1 = mb[col + 1];
            sv[nt][0] = sv[nt][0] * scale + mb0;
            sv[nt][1] = sv[nt][1] * scale + mb1;
            sv[nt][2] = sv[nt][2] * scale + mb0;
            sv[nt][3] = sv[nt][3] * scale + mb1;
            rm0 = fmaxf(rm0, fmaxf(sv[nt][0], sv[nt][1]));
            rm1 = fmaxf(rm1, fmaxf(sv[nt][2], sv[nt][3]));
        }
        #pragma unroll
        for (int ox = 1; ox <= 2; ox <<= 1) {
            rm0 = fmaxf(rm0, __shfl_xor_sync(0xffffffffu, rm0, ox));
            rm1 = fmaxf(rm1, __shfl_xor_sync(0xffffffffu, rm1, ox));
        }
        float mn0 = fmaxf(m2[0], rm0), mn1 = fmaxf(m2[1], rm1);
        float f0 = __expf(m2[0] - mn0), f1 = __expf(m2[1] - mn1);
        m2[0] = mn0; m2[1] = mn1;

        float rs0 = 0.0f, rs1 = 0.0f;
        #pragma unroll
        for (int nt = 0; nt < 8; nt++) {
            sv[nt][0] = __expf(sv[nt][0] - mn0);
            sv[nt][1] = __expf(sv[nt][1] - mn0);
            sv[nt][2] = __expf(sv[nt][2] - mn1);
            sv[nt][3] = __expf(sv[nt][3] - mn1);
            rs0 += sv[nt][0] + sv[nt][1];
            rs1 += sv[nt][2] + sv[nt][3];
        }
        #pragma unroll
        for (int ox = 1; ox <= 2; ox <<= 1) {
            rs0 += __shfl_xor_sync(0xffffffffu, rs0, ox);
            rs1 += __shfl_xor_sync(0xffffffffu, rs1, ox);
        }
        l2[0] = l2[0] * f0 + rs0;
        l2[1] = l2[1] * f1 + rs1;
        #pragma unroll
        for (int nt = 0; nt < 8; nt++) {
            o[nt][0] *= f0; o[nt][1] *= f0;
            o[nt][2] *= f1; o[nt][3] *= f1;
        }

        #pragma unroll
        for (int s = 0; s < 4; s++) {
            uint32_t a[4];
            a[0] = ph2(sv[2 * s][0],     sv[2 * s][1]);
            a[1] = ph2(sv[2 * s][2],     sv[2 * s][3]);
            a[2] = ph2(sv[2 * s + 1][0], sv[2 * s + 1][1]);
            a[3] = ph2(sv[2 * s + 1][2], sv[2 * s + 1][3]);
            #pragma unroll
            for (int nt = 0; nt < 8; nt++) {
                int bb = (nt * 8 + g) * AQP + s * 8 + t;
                mma16816h(o[nt], a, Vt[bb], Vt[bb + 4]);
            }
        }
    }

    float i0 = 1.0f / l2[0], i1 = 1.0f / l2[1];
    #pragma unroll
    for (int nt = 0; nt < 8; nt++) {
        size_t row0 = (size_t)(b * SEQ + q0 + qrow + g) * DMODEL + h * HDIM + nt * 8 + t * 2;
        size_t row1 = row0 + 8 * DMODEL;
        *(uint32_t*)(oh + row0) = ph2(o[nt][0] * i0, o[nt][1] * i0);
        *(uint32_t*)(oh + row1) = ph2(o[nt][2] * i1, o[nt][3] * i1);
    }
}

// ---------------- host driver ----------------
extern "C" void kernel_launch(void* const* d_in, const int* in_sizes, int n_in,
                              void* d_out, int out_size)
{
    const float* x     = (const float*)d_in[0];
    const int*   mask  = (const int*)d_in[1];
    const float* Wq    = (const float*)d_in[2];
    const float* Wk    = (const float*)d_in[3];
    const float* Wv    = (const float*)d_in[4];
    const float* Wo    = (const float*)d_in[5];
    const float* ln1_g = (const float*)d_in[6];
    const float* ln1_b = (const float*)d_in[7];
    const float* ln2_g = (const float*)d_in[8];
    const float* ln2_b = (const float*)d_in[9];
    const float* W1    = (const float*)d_in[10];
    const float* b1    = (const float*)d_in[11];
    const float* W2    = (const float*)d_in[12];
    const float* b2    = (const float*)d_in[13];

    static float *px = nullptr;
    static __half *pqkvh, *plnh, *ppah, *ppfh, *pwh;
    if (!px) {
        cudaGetSymbolAddress((void**)&pqkvh, g_qkvh);
        cudaGetSymbolAddress((void**)&plnh, g_lnh);
        cudaGetSymbolAddress((void**)&ppah, g_pah);
        cudaGetSymbolAddress((void**)&ppfh, g_pfh);
        cudaGetSymbolAddress((void**)&pwh, g_wth);
        cudaFuncSetAttribute(attn_mma, cudaFuncAttributeMaxDynamicSharedMemorySize, ATT_SMEM);
        cudaFuncSetAttribute(gemm_pipe<0,0,1>, cudaFuncAttributeMaxDynamicSharedMemorySize, GEMM_SMEM3);
        cudaFuncSetAttribute(gemm_pipe<1,1,0>, cudaFuncAttributeMaxDynamicSharedMemorySize, GEMM_SMEM3);
        cudaFuncSetAttribute(gemm_pipe<2,0,1>, cudaFuncAttributeMaxDynamicSharedMemorySize, GEMM_SMEM3);
        cudaFuncSetAttribute(gemm_pipe<3,1,0>, cudaFuncAttributeMaxDynamicSharedMemorySize, GEMM_SMEM3);
        cudaGetSymbolAddress((void**)&px, g_x);
    }

    // ---- fused weight convert+transpose (single launch) ----
    {
        dim3 blk(32, 8);
        wconv_all<<<WCONV_BLOCKS, blk>>>(Wq, Wk, Wv, Wo, W1, W2, pwh);
    }

    posenc_kernel<<<(MROWS * DMODEL + 255) / 256, 256>>>(x, px);

    dim3 gQ(QKVN / 128,   MROWS / 128);
    dim3 gD(DMODEL / 128, MROWS / 128);
    dim3 gF(DFF / 128,    MROWS / 128);
    dim3 gA(SEQ / 128, BATCH * NHEAD);

    for (int l = 0; l < NLAYERS; l++) {
        size_t base = (size_t)l * WLAYER;
        const __half *qkvh = pwh + base;
        const __half *ohp  = pwh + base + 786432;
        const __half *f1h  = pwh + base + 1048576;
        const __half *f2h  = pwh + base + 2097152;

        ln_kernel<<<MROWS, 128>>>(px, ln1_g + l * DMODEL, ln1_b + l * DMODEL, plnh);

        gemm_pipe<0,0,1><<<gQ, 256, GEMM_SMEM3>>>(plnh, qkvh, nullptr, nullptr,
                                                  nullptr, pqkvh, DMODEL, QKVN);

        attn_mma<<<gA, 256, ATT_SMEM>>>(pqkvh, mask, ppah);

        gemm_pipe<1,1,0><<<gD, 256, GEMM_SMEM3>>>(ppah, ohp, nullptr, px,
                                                  px, nullptr, DMODEL, DMODEL);

        ln_kernel<<<MROWS, 128>>>(px, ln2_g + l * DMODEL, ln2_b + l * DMODEL, plnh);

        gemm_pipe<2,0,1><<<gF, 256, GEMM_SMEM3>>>(plnh, f1h, b1 + (size_t)l * DFF, nullptr,
                                                  nullptr, ppfh, DMODEL, DFF);

        float* outp = (l == NLAYERS - 1) ? (float*)d_out : px;
        gemm_pipe<3,1,0><<<gD, 256, GEMM_SMEM3>>>(ppfh, f2h, b2 + (size_t)l * DMODEL, px,
                                                  outp, nullptr, DFF, DMODEL);
    }
}

// round 15
// speedup vs baseline: 1.0947x; 1.0947x over previous
#include <cuda_runtime.h>
#include <cuda_fp16.h>
#include <math.h>
#include <stdint.h>

// ---------------- problem constants ----------------
#define NLAYERS 4
#define DMODEL  512
#define NHEAD   8
#define HDIM    64
#define DFF     2048
#define BATCH   8
#define SEQ     1024
#define MROWS   (BATCH*SEQ)
#define LN_EPS  1e-3f
#define QKVN    1536

#define WLAYER  3145728
#define WT_ELEMS (NLAYERS*WLAYER)

// ---------------- device scratch ----------------
__device__ float g_x   [MROWS*DMODEL];
__device__ __half g_qkvh[MROWS*QKVN];
__device__ __half g_lnh[MROWS*DMODEL];
__device__ __half g_pah[MROWS*DMODEL];
__device__ __half g_pfh[MROWS*DFF];
__device__ uint4 g_wth [WT_ELEMS/8];     // weights fp16, [N][K] transposed

extern __shared__ char dyn_smem[];

// ---------------- helpers ----------------
__device__ __forceinline__ void mma16816h(float* c, const uint32_t* a, uint32_t b0, uint32_t b1) {
    asm volatile(
        "mma.sync.aligned.m16n8k16.row.col.f32.f16.f16.f32 "
        "{%0,%1,%2,%3}, {%4,%5,%6,%7}, {%8,%9}, {%0,%1,%2,%3};"
        : "+f"(c[0]), "+f"(c[1]), "+f"(c[2]), "+f"(c[3])
        : "r"(a[0]), "r"(a[1]), "r"(a[2]), "r"(a[3]), "r"(b0), "r"(b1));
}
#define LDSM4(r0, r1, r2, r3, addr) \
    asm volatile("ldmatrix.sync.aligned.m8n8.x4.shared.b16 {%0,%1,%2,%3}, [%4];" \
        : "=r"(r0), "=r"(r1), "=r"(r2), "=r"(r3) : "r"(addr))

__device__ __forceinline__ void cpasync16(uint32_t saddr, const void* gptr) {
    asm volatile("cp.async.cg.shared.global [%0], [%1], 16;" :: "r"(saddr), "l"(gptr));
}
__device__ __forceinline__ uint32_t smem_u32(const void* p) {
    uint32_t a;
    asm("{ .reg .u64 t; cvta.to.shared.u64 t, %1; cvt.u32.u64 %0, t; }" : "=r"(a) : "l"(p));
    return a;
}
__device__ __forceinline__ void cp_commit() { asm volatile("cp.async.commit_group;" ::: "memory"); }
__device__ __forceinline__ void cp_wait2()  { asm volatile("cp.async.wait_group 2;"  ::: "memory"); }

__device__ __forceinline__ uint32_t ph2(float x, float y) {
    __half2 h = __floats2half2_rn(x, y);
    return *(uint32_t*)&h;
}
__device__ __forceinline__ uint32_t prmt(uint32_t a, uint32_t b, uint32_t s) {
    uint32_t d;
    asm("prmt.b32 %0, %1, %2, %3;" : "=r"(d) : "r"(a), "r"(b), "r"(s));
    return d;
}

// ---------------- positional encoding ----------------
__global__ void posenc_kernel(const float* __restrict__ x, float* __restrict__ out) {
    int idx = blockIdx.x * 256 + threadIdx.x;
    if (idx >= MROWS * DMODEL) return;
    int d = idx & (DMODEL - 1);
    int s = (idx / DMODEL) & (SEQ - 1);
    const int half = DMODEL / 2;
    float val;
    if (d < half) {
        float ang = (float)s * expf(-logf(10000.0f) * (2.0f * (float)d / (float)DMODEL));
        val = sinf(ang);
    } else {
        float j = (float)(d - half);
        float ang = (float)s * expf(-logf(10000.0f) * (2.0f * j / (float)DMODEL));
        val = cosf(ang);
    }
    out[idx] = x[idx] + val;
}

// ---------------- layernorm -> fp16 ----------------
__global__ void ln_kernel(const float* __restrict__ x, const float* __restrict__ gamma,
                          const float* __restrict__ beta, __half* __restrict__ oh) {
    int row = blockIdx.x;
    int t = threadIdx.x;
    const float4* xr = (const float4*)(x + (size_t)row * DMODEL);
    float4 v = xr[t];

    __shared__ float red1[4];
    __shared__ float red2[4];

    float s = v.x + v.y + v.z + v.w;
    #pragma unroll
    for (int o = 16; o > 0; o >>= 1) s += __shfl_xor_sync(0xffffffffu, s, o);
    if ((t & 31) == 0) red1[t >> 5] = s;
    __syncthreads();
    float mean = (red1[0] + red1[1] + red1[2] + red1[3]) * (1.0f / DMODEL);

    float dx = v.x - mean, dy = v.y - mean, dz = v.z - mean, dw = v.w - mean;
    float s2 = dx*dx + dy*dy + dz*dz + dw*dw;
    #pragma unroll
    for (int o = 16; o > 0; o >>= 1) s2 += __shfl_xor_sync(0xffffffffu, s2, o);
    if ((t & 31) == 0) red2[t >> 5] = s2;
    __syncthreads();
    float var = (red2[0] + red2[1] + red2[2] + red2[3]) * (1.0f / DMODEL);
    float rs = rsqrtf(var + LN_EPS);

    float4 g4 = ((const float4*)gamma)[t];
    float4 b4 = ((const float4*)beta)[t];
    float o0 = dx * rs * g4.x + b4.x;
    float o1 = dy * rs * g4.y + b4.y;
    float o2 = dz * rs * g4.z + b4.z;
    float o3 = dw * rs * g4.w + b4.w;
    *(uint2*)(oh + (size_t)row * DMODEL + t * 4) =
        make_uint2(ph2(o0, o1), ph2(o2, o3));
}

// ---------------- fused weight convert+transpose: ALL 24 matrices, one launch ----------------
#define WCONV_BLOCKS (NLAYERS * 3072)

__global__ void wconv_all(const float* __restrict__ Wq, const float* __restrict__ Wk,
                          const float* __restrict__ Wv, const float* __restrict__ Wo,
                          const float* __restrict__ W1, const float* __restrict__ W2,
                          __half* __restrict__ Oh) {
    __shared__ float tile[32][33];
    int bid = blockIdx.x;
    int l = bid / 3072;
    int r = bid - l * 3072;

    const float* src;
    size_t dstoff;
    int K, N, tx, ty;
    if (r < 1024) {
        int mat = r >> 8;
        int t = r & 255;
        K = 512; N = 512;
        src = (mat == 0 ? Wq : mat == 1 ? Wk : mat == 2 ? Wv : Wo) + (size_t)l * 262144;
        dstoff = (size_t)l * WLAYER + (size_t)mat * 262144;
        tx = t & 15; ty = t >> 4;
    } else if (r < 2048) {
        int t = r - 1024;
        K = 512; N = 2048;
        src = W1 + (size_t)l * 1048576;
        dstoff = (size_t)l * WLAYER + 1048576;
        tx = t & 63; ty = t >> 6;
    } else {
        int t = r - 2048;
        K = 2048; N = 512;
        src = W2 + (size_t)l * 1048576;
        dstoff = (size_t)l * WLAYER + 2097152;
        tx = t & 15; ty = t >> 4;
    }

    int tn = tx * 32, tk = ty * 32;
    int x = threadIdx.x, y = threadIdx.y;     // (32, 8)
    #pragma unroll
    for (int i = 0; i < 4; i++)
        tile[y + i * 8][x] = src[(size_t)(tk + y + i * 8) * N + tn + x];
    __syncthreads();
    __half* dst = Oh + dstoff;
    #pragma unroll
    for (int i = 0; i < 4; i++) {
        int nl = y + i * 8;
        dst[(size_t)(tn + nl) * K + tk + x] = __float2half_rn(tile[x][nl]);
    }
}

// ---------------- 4-stage pipelined fp16 mma GEMM with ldmatrix, 128x128 tile (R13 config) ----------------
#define BKP 20
#define ARR_STRIDE (128 * BKP)
#define STAGE_BYTES (2 * ARR_STRIDE * 4)      // 20480 (A + B)
#define GEMM_SMEM4 (4 * STAGE_BYTES)          // 81920

template<int EPI, int OUTF32, int OUTF16>
__global__ __launch_bounds__(256) void gemm_pipe(
    const __half* __restrict__ Ah,
    const __half* __restrict__ Wh,
    const float* __restrict__ bias, const float* __restrict__ res,
    float* __restrict__ Cf, __half* __restrict__ Ch,
    int K, int N)
{
    uint32_t sbase = smem_u32(dyn_smem);
    int tid = threadIdx.x;
    int lane = tid & 31, wid = tid >> 5;
    int wm = wid >> 1, wn = wid & 1;
    int m0 = blockIdx.y * 128, n0 = blockIdx.x * 128;
    int g = lane >> 2, t = lane & 3;

    int lrow = tid >> 1;
    int lhalf = tid & 1;

    const __half* agh = Ah + (size_t)(m0 + lrow) * K;
    const __half* bgh = Wh + (size_t)(n0 + lrow) * K;
    uint32_t srow = sbase + (uint32_t)(lrow * BKP) * 4;

    uint32_t a_lane = sbase + (uint32_t)((wm * 32 + (lane & 15)) * BKP) * 4 + (uint32_t)(lane >> 4) * 16;
    uint32_t b_lane = sbase + (uint32_t)ARR_STRIDE * 4
                    + (uint32_t)((wn * 64 + (lane >> 4) * 8 + (lane & 7)) * BKP) * 4
                    + (uint32_t)((lane >> 3) & 1) * 16;

    const int nkb = K >> 5;

    auto issue_load = [&](int k) {
        if (k < nkb) {
            int kb = k << 5;
            uint32_t so = srow + (uint32_t)(k & 3) * STAGE_BYTES;
            #pragma unroll
            for (int p = 0; p < 2; p++) {
                int q = lhalf * 2 + p;
                int ge = kb + q * 8;
                uint32_t sb2 = so + (uint32_t)(q * 16);
                cpasync16(sb2,                  agh + ge);
                cpasync16(sb2 + ARR_STRIDE * 4, bgh + ge);
            }
        }
        cp_commit();
    };

    float c[2][8][4];
    #pragma unroll
    for (int mt = 0; mt < 2; mt++)
        #pragma unroll
        for (int nt = 0; nt < 8; nt++)
            #pragma unroll
            for (int e = 0; e < 4; e++) c[mt][nt][e] = 0.0f;

    issue_load(0);
    issue_load(1);
    issue_load(2);

    for (int k = 0; k < nkb; k++) {
        cp_wait2();
        __syncthreads();
        issue_load(k + 3);

        uint32_t so = (uint32_t)(k & 3) * STAGE_BYTES;
        uint32_t abase = a_lane + so;
        uint32_t bbase = b_lane + so;

        #pragma unroll
        for (int s = 0; s < 2; s++) {
            uint32_t acol = (uint32_t)(s * 32);
            uint32_t a0[4], a1[4];
            LDSM4(a0[0], a0[1], a0[2], a0[3], abase + acol);
            LDSM4(a1[0], a1[1], a1[2], a1[3], abase + acol + 16 * BKP * 4);
            #pragma unroll
            for (int p = 0; p < 4; p++) {
                uint32_t b0, b1, b2, b3;
                LDSM4(b0, b1, b2, b3, bbase + acol + (uint32_t)(p * 16 * BKP * 4));
                mma16816h(c[0][2 * p],     a0, b0, b1);
                mma16816h(c[1][2 * p],     a1, b0, b1);
                mma16816h(c[0][2 * p + 1], a0, b2, b3);
                mma16816h(c[1][2 * p + 1], a1, b2, b3);
            }
        }
    }

    #pragma unroll
    for (int mt = 0; mt < 2; mt++) {
        #pragma unroll
        for (int nt = 0; nt < 8; nt++) {
            int row = m0 + wm * 32 + mt * 16 + g;
            int col = n0 + wn * 64 + nt * 8 + t * 2;
            float2 v1 = make_float2(c[mt][nt][0], c[mt][nt][1]);
            float2 v2 = make_float2(c[mt][nt][2], c[mt][nt][3]);
            if (EPI == 2 || EPI == 3) {
                float2 bb = *(const float2*)(bias + col);
                v1.x += bb.x; v1.y += bb.y;
                v2.x += bb.x; v2.y += bb.y;
            }
            if (EPI == 2) {
                v1.x = fmaxf(v1.x, 0.0f); v1.y = fmaxf(v1.y, 0.0f);
                v2.x = fmaxf(v2.x, 0.0f); v2.y = fmaxf(v2.y, 0.0f);
            }
            if (EPI == 1 || EPI == 3) {
                float2 r1 = *(const float2*)(res + (size_t)row * N + col);
                float2 r2 = *(const float2*)(res + (size_t)(row + 8) * N + col);
                v1.x += r1.x; v1.y += r1.y;
                v2.x += r2.x; v2.y += r2.y;
            }
            if (OUTF32) {
                *(float2*)(Cf + (size_t)row * N + col) = v1;
                *(float2*)(Cf + (size_t)(row + 8) * N + col) = v2;
            }
            if (OUTF16) {
                *(uint32_t*)(Ch + (size_t)row * N + col) = ph2(v1.x, v1.y);
                *(uint32_t*)(Ch + (size_t)(row + 8) * N + col) = ph2(v2.x, v2.y);
            }
        }
    }
}

// ---------------- tensor-core flash attention (fp16 in/out) ----------------
#define AQP 36
#define ATT_SMEM (((128 + 64 + 64) * AQP) * 4 + 256)

__global__ __launch_bounds__(256) void attn_mma(
    const __half* __restrict__ qkv, const int* __restrict__ mask,
    __half* __restrict__ oh)
{
    uint32_t* Qs = (uint32_t*)dyn_smem;
    uint32_t* Ks = Qs + 128 * AQP;
    uint32_t* Vt = Ks + 64 * AQP;
    float* mb = (float*)(Vt + 64 * AQP);

    int tid = threadIdx.x;
    int lane = tid & 31, wid = tid >> 5;
    int g = lane >> 2, t = lane & 3;
    int b = blockIdx.y >> 3, h = blockIdx.y & 7;
    int q0 = blockIdx.x * 128;
    const float scale = 0.125f;

    #pragma unroll
    for (int p = 0; p < 8; p++) {
        int idx = tid + p * 256;
        int row = idx >> 4, c4 = (idx & 15) * 4;
        uint2 f = *(const uint2*)(qkv + (size_t)(b * SEQ + q0 + row) * QKVN + h * HDIM + c4);
        Qs[row * AQP + c4 / 2]     = f.x;
        Qs[row * AQP + c4 / 2 + 1] = f.y;
    }

    float m2[2] = {-INFINITY, -INFINITY};
    float l2[2] = {0.0f, 0.0f};
    float o[8][4];
    #pragma unroll
    for (int nt = 0; nt < 8; nt++)
        #pragma unroll
        for (int e = 0; e < 4; e++) o[nt][e] = 0.0f;

    int qrow = wid * 16;

    for (int kt = 0; kt < SEQ / 64; kt++) {
        __syncthreads();
        #pragma unroll
        for (int p = 0; p < 4; p++) {
            int idx = tid + p * 256;
            int row = idx >> 4, c4 = (idx & 15) * 4;
            uint2 f = *(const uint2*)(qkv + (size_t)(b * SEQ + kt * 64 + row) * QKVN + DMODEL + h * HDIM + c4);
            Ks[row * AQP + c4 / 2]     = f.x;
            Ks[row * AQP + c4 / 2 + 1] = f.y;
        }
        #pragma unroll
        for (int it = 0; it < 2; it++) {
            int hd0 = ((tid >> 5) + it * 8) * 4;
            int kp = tid & 31;
            const __half* v0 = qkv + (size_t)(b * SEQ + kt * 64 + kp * 2) * QKVN + 2 * DMODEL + h * HDIM + hd0;
            uint2 fa = *(const uint2*)v0;
            uint2 fb = *(const uint2*)(v0 + QKVN);
            Vt[(hd0 + 0) * AQP + kp] = prmt(fa.x, fb.x, 0x5410);
            Vt[(hd0 + 1) * AQP + kp] = prmt(fa.x, fb.x, 0x7632);
            Vt[(hd0 + 2) * AQP + kp] = prmt(fa.y, fb.y, 0x5410);
            Vt[(hd0 + 3) * AQP + kp] = prmt(fa.y, fb.y, 0x7632);
        }
        if (tid < 64)
            mb[tid] = (mask[b * SEQ + kt * 64 + tid] != 0) ? 0.0f : -1e9f;
        __syncthreads();

        float sv[8][4];
        #pragma unroll
        for (int nt = 0; nt < 8; nt++)
            #pragma unroll
            for (int e = 0; e < 4; e++) sv[nt][e] = 0.0f;

        #pragma unroll
        for (int s = 0; s < 4; s++) {
            uint32_t a[4];
            int ab = (qrow + g) * AQP + s * 8 + t;
            a[0] = Qs[ab];
            a[1] = Qs[ab + 8 * AQP];
            a[2] = Qs[ab + 4];
            a[3] = Qs[ab + 8 * AQP + 4];
            #pragma unroll
            for (int nt = 0; nt < 8; nt++) {
                int bb = (nt * 8 + g) * AQP + s * 8 + t;
                mma16816h(sv[nt], a, Ks[bb], Ks[bb + 4]);
            }
        }

        float rm0 = -INFINITY, rm1 = -INFINITY;
        #pragma unroll
        for (int nt = 0; nt < 8; nt++) {
            int col = nt * 8 + t * 2;
            float mb0 = mb[col], mb1 = mb[col + 1];
            sv[nt][0] = sv[nt][0] * scale + mb0;
            sv[nt][1] = sv[nt][1] * scale + mb1;
            sv[nt][2] = sv[nt][2] * scale + mb0;
            sv[nt][3] = sv[nt][3] * scale + mb1;
            rm0 = fmaxf(rm0, fmaxf(sv[nt][0], sv[nt][1]));
            rm1 = fmaxf(rm1, fmaxf(sv[nt][2], sv[nt][3]));
        }
        #pragma unroll
        for (int ox = 1; ox <= 2; ox <<= 1) {
            rm0 = fmaxf(rm0, __shfl_xor_sync(0xffffffffu, rm0, ox));
            rm1 = fmaxf(rm1, __shfl_xor_sync(0xffffffffu, rm1, ox));
        }
        float mn0 = fmaxf(m2[0], rm0), mn1 = fmaxf(m2[1], rm1);
        float f0 = __expf(m2[0] - mn0), f1 = __expf(m2[1] - mn1);
        m2[0] = mn0; m2[1] = mn1;

        float rs0 = 0.0f, rs1 = 0.0f;
        #pragma unroll
        for (int nt = 0; nt < 8; nt++) {
            sv[nt][0] = __expf(sv[nt][0] - mn0);
            sv[nt][1] = __expf(sv[nt][1] - mn0);
            sv[nt][2] = __expf(sv[nt][2] - mn1);
            sv[nt][3] = __expf(sv[nt][3] - mn1);
            rs0 += sv[nt][0] + sv[nt][1];
            rs1 += sv[nt][2] + sv[nt][3];
        }
        #pragma unroll
        for (int ox = 1; ox <= 2; ox <<= 1) {
            rs0 += __shfl_xor_sync(0xffffffffu, rs0, ox);
            rs1 += __shfl_xor_sync(0xffffffffu, rs1, ox);
        }
        l2[0] = l2[0] * f0 + rs0;
        l2[1] = l2[1] * f1 + rs1;
        #pragma unroll
        for (int nt = 0; nt < 8; nt++) {
            o[nt][0] *= f0; o[nt][1] *= f0;
            o[nt][2] *= f1; o[nt][3] *= f1;
        }

        #pragma unroll
        for (int s = 0; s < 4; s++) {
            uint32_t a[4];
            a[0] = ph2(sv[2 * s][0],     sv[2 * s][1]);
            a[1] = ph2(sv[2 * s][2],     sv[2 * s][3]);
            a[2] = ph2(sv[2 * s + 1][0], sv[2 * s + 1][1]);
            a[3] = ph2(sv[2 * s + 1][2], sv[2 * s + 1][3]);
            #pragma unroll
            for (int nt = 0; nt < 8; nt++) {
                int bb = (nt * 8 + g) * AQP + s * 8 + t;
                mma16816h(o[nt], a, Vt[bb], Vt[bb + 4]);
            }
        }
    }

    float i0 = 1.0f / l2[0], i1 = 1.0f / l2[1];
    #pragma unroll
    for (int nt = 0; nt < 8; nt++) {
        size_t row0 = (size_t)(b * SEQ + q0 + qrow + g) * DMODEL + h * HDIM + nt * 8 + t * 2;
        size_t row1 = row0 + 8 * DMODEL;
        *(uint32_t*)(oh + row0) = ph2(o[nt][0] * i0, o[nt][1] * i0);
        *(uint32_t*)(oh + row1) = ph2(o[nt][2] * i1, o[nt][3] * i1);
    }
}

// ---------------- host driver ----------------
extern "C" void kernel_launch(void* const* d_in, const int* in_sizes, int n_in,
                              void* d_out, int out_size)
{
    const float* x     = (const float*)d_in[0];
    const int*   mask  = (const int*)d_in[1];
    const float* Wq    = (const float*)d_in[2];
    const float* Wk    = (const float*)d_in[3];
    const float* Wv    = (const float*)d_in[4];
    const float* Wo    = (const float*)d_in[5];
    const float* ln1_g = (const float*)d_in[6];
    const float* ln1_b = (const float*)d_in[7];
    const float* ln2_g = (const float*)d_in[8];
    const float* ln2_b = (const float*)d_in[9];
    const float* W1    = (const float*)d_in[10];
    const float* b1    = (const float*)d_in[11];
    const float* W2    = (const float*)d_in[12];
    const float* b2    = (const float*)d_in[13];

    static float *px = nullptr;
    static __half *pqkvh, *plnh, *ppah, *ppfh, *pwh;
    if (!px) {
        cudaGetSymbolAddress((void**)&pqkvh, g_qkvh);
        cudaGetSymbolAddress((void**)&plnh, g_lnh);
        cudaGetSymbolAddress((void**)&ppah, g_pah);
        cudaGetSymbolAddress((void**)&ppfh, g_pfh);
        cudaGetSymbolAddress((void**)&pwh, g_wth);
        cudaFuncSetAttribute(attn_mma, cudaFuncAttributeMaxDynamicSharedMemorySize, ATT_SMEM);
        cudaFuncSetAttribute(gemm_pipe<0,0,1>, cudaFuncAttributeMaxDynamicSharedMemorySize, GEMM_SMEM4);
        cudaFuncSetAttribute(gemm_pipe<1,1,0>, cudaFuncAttributeMaxDynamicSharedMemorySize, GEMM_SMEM4);
        cudaFuncSetAttribute(gemm_pipe<2,0,1>, cudaFuncAttributeMaxDynamicSharedMemorySize, GEMM_SMEM4);
        cudaFuncSetAttribute(gemm_pipe<3,1,0>, cudaFuncAttributeMaxDynamicSharedMemorySize, GEMM_SMEM4);
        cudaGetSymbolAddress((void**)&px, g_x);
    }

    // ---- fused weight convert+transpose (single launch) ----
    {
        dim3 blk(32, 8);
        wconv_all<<<WCONV_BLOCKS, blk>>>(Wq, Wk, Wv, Wo, W1, W2, pwh);
    }

    posenc_kernel<<<(MROWS * DMODEL + 255) / 256, 256>>>(x, px);

    dim3 gQ(QKVN / 128,   MROWS / 128);
    dim3 gD(DMODEL / 128, MROWS / 128);
    dim3 gF(DFF / 128,    MROWS / 128);
    dim3 gA(SEQ / 128, BATCH * NHEAD);

    for (int l = 0; l < NLAYERS; l++) {
        size_t base = (size_t)l * WLAYER;
        const __half *qkvh = pwh + base;
        const __half *ohp  = pwh + base + 786432;
        const __half *f1h  = pwh + base + 1048576;
        const __half *f2h  = pwh + base + 2097152;

        ln_kernel<<<MROWS, 128>>>(px, ln1_g + l * DMODEL, ln1_b + l * DMODEL, plnh);

        gemm_pipe<0,0,1><<<gQ, 256, GEMM_SMEM4>>>(plnh, qkvh, nullptr, nullptr,
                                                  nullptr, pqkvh, DMODEL, QKVN);

        attn_mma<<<gA, 256, ATT_SMEM>>>(pqkvh, mask, ppah);

        gemm_pipe<1,1,0><<<gD, 256, GEMM_SMEM4>>>(ppah, ohp, nullptr, px,
                                                  px, nullptr, DMODEL, DMODEL);

        ln_kernel<<<MROWS, 128>>>(px, ln2_g + l * DMODEL, ln2_b + l * DMODEL, plnh);

        gemm_pipe<2,0,1><<<gF, 256, GEMM_SMEM4>>>(plnh, f1h, b1 + (size_t)l * DFF, nullptr,
                                                  nullptr, ppfh, DMODEL, DFF);

        float* outp = (l == NLAYERS - 1) ? (float*)d_out : px;
        gemm_pipe<3,1,0><<<gD, 256, GEMM_SMEM4>>>(ppfh, f2h, b2 + (size_t)l * DMODEL, px,
                                                  outp, nullptr, DFF, DMODEL);
    }
}

// round 16
// speedup vs baseline: 1.2486x; 1.1406x over previous
#include <cuda_runtime.h>
#include <cuda_fp16.h>
#include <math.h>
#include <stdint.h>

// ---------------- problem constants ----------------
#define NLAYERS 4
#define DMODEL  512
#define NHEAD   8
#define HDIM    64
#define DFF     2048
#define BATCH   8
#define SEQ     1024
#define MROWS   (BATCH*SEQ)
#define LN_EPS  1e-3f
#define QKVN    1536

#define WLAYER  3145728
#define WT_ELEMS (NLAYERS*WLAYER)

// ---------------- device scratch ----------------
__device__ float g_x   [MROWS*DMODEL];
__device__ __half g_qkvh[MROWS*QKVN];
__device__ __half g_lnh[MROWS*DMODEL];
__device__ __half g_pah[MROWS*DMODEL];
__device__ __half g_pfh[MROWS*DFF];
__device__ uint4 g_wth [WT_ELEMS/8];     // weights fp16, [N][K] transposed

extern __shared__ char dyn_smem[];

// ---------------- helpers ----------------
__device__ __forceinline__ void mma16816h(float* c, const uint32_t* a, uint32_t b0, uint32_t b1) {
    asm volatile(
        "mma.sync.aligned.m16n8k16.row.col.f32.f16.f16.f32 "
        "{%0,%1,%2,%3}, {%4,%5,%6,%7}, {%8,%9}, {%0,%1,%2,%3};"
        : "+f"(c[0]), "+f"(c[1]), "+f"(c[2]), "+f"(c[3])
        : "r"(a[0]), "r"(a[1]), "r"(a[2]), "r"(a[3]), "r"(b0), "r"(b1));
}
#define LDSM4(r0, r1, r2, r3, addr) \
    asm volatile("ldmatrix.sync.aligned.m8n8.x4.shared.b16 {%0,%1,%2,%3}, [%4];" \
        : "=r"(r0), "=r"(r1), "=r"(r2), "=r"(r3) : "r"(addr))
#define LDSM4T(r0, r1, r2, r3, addr) \
    asm volatile("ldmatrix.sync.aligned.m8n8.x4.trans.shared.b16 {%0,%1,%2,%3}, [%4];" \
        : "=r"(r0), "=r"(r1), "=r"(r2), "=r"(r3) : "r"(addr))

__device__ __forceinline__ void cpasync16(uint32_t saddr, const void* gptr) {
    asm volatile("cp.async.cg.shared.global [%0], [%1], 16;" :: "r"(saddr), "l"(gptr));
}
__device__ __forceinline__ uint32_t smem_u32(const void* p) {
    uint32_t a;
    asm("{ .reg .u64 t; cvta.to.shared.u64 t, %1; cvt.u32.u64 %0, t; }" : "=r"(a) : "l"(p));
    return a;
}
__device__ __forceinline__ void cp_commit() { asm volatile("cp.async.commit_group;" ::: "memory"); }
__device__ __forceinline__ void cp_wait0()  { asm volatile("cp.async.wait_group 0;"  ::: "memory"); }
__device__ __forceinline__ void cp_wait2()  { asm volatile("cp.async.wait_group 2;"  ::: "memory"); }

__device__ __forceinline__ uint32_t ph2(float x, float y) {
    __half2 h = __floats2half2_rn(x, y);
    return *(uint32_t*)&h;
}

// ---------------- positional encoding ----------------
__global__ void posenc_kernel(const float* __restrict__ x, float* __restrict__ out) {
    int idx = blockIdx.x * 256 + threadIdx.x;
    if (idx >= MROWS * DMODEL) return;
    int d = idx & (DMODEL - 1);
    int s = (idx / DMODEL) & (SEQ - 1);
    const int half = DMODEL / 2;
    float val;
    if (d < half) {
        float ang = (float)s * expf(-logf(10000.0f) * (2.0f * (float)d / (float)DMODEL));
        val = sinf(ang);
    } else {
        float j = (float)(d - half);
        float ang = (float)s * expf(-logf(10000.0f) * (2.0f * j / (float)DMODEL));
        val = cosf(ang);
    }
    out[idx] = x[idx] + val;
}

// ---------------- layernorm -> fp16 ----------------
__global__ void ln_kernel(const float* __restrict__ x, const float* __restrict__ gamma,
                          const float* __restrict__ beta, __half* __restrict__ oh) {
    int row = blockIdx.x;
    int t = threadIdx.x;
    const float4* xr = (const float4*)(x + (size_t)row * DMODEL);
    float4 v = xr[t];

    __shared__ float red1[4];
    __shared__ float red2[4];

    float s = v.x + v.y + v.z + v.w;
    #pragma unroll
    for (int o = 16; o > 0; o >>= 1) s += __shfl_xor_sync(0xffffffffu, s, o);
    if ((t & 31) == 0) red1[t >> 5] = s;
    __syncthreads();
    float mean = (red1[0] + red1[1] + red1[2] + red1[3]) * (1.0f / DMODEL);

    float dx = v.x - mean, dy = v.y - mean, dz = v.z - mean, dw = v.w - mean;
    float s2 = dx*dx + dy*dy + dz*dz + dw*dw;
    #pragma unroll
    for (int o = 16; o > 0; o >>= 1) s2 += __shfl_xor_sync(0xffffffffu, s2, o);
    if ((t & 31) == 0) red2[t >> 5] = s2;
    __syncthreads();
    float var = (red2[0] + red2[1] + red2[2] + red2[3]) * (1.0f / DMODEL);
    float rs = rsqrtf(var + LN_EPS);

    float4 g4 = ((const float4*)gamma)[t];
    float4 b4 = ((const float4*)beta)[t];
    float o0 = dx * rs * g4.x + b4.x;
    float o1 = dy * rs * g4.y + b4.y;
    float o2 = dz * rs * g4.z + b4.z;
    float o3 = dw * rs * g4.w + b4.w;
    *(uint2*)(oh + (size_t)row * DMODEL + t * 4) =
        make_uint2(ph2(o0, o1), ph2(o2, o3));
}

// ---------------- fused weight convert+transpose: ALL 24 matrices, one launch ----------------
#define WCONV_BLOCKS (NLAYERS * 3072)

__global__ void wconv_all(const float* __restrict__ Wq, const float* __restrict__ Wk,
                          const float* __restrict__ Wv, const float* __restrict__ Wo,
                          const float* __restrict__ W1, const float* __restrict__ W2,
                          __half* __restrict__ Oh) {
    __shared__ float tile[32][33];
    int bid = blockIdx.x;
    int l = bid / 3072;
    int r = bid - l * 3072;

    const float* src;
    size_t dstoff;
    int K, N, tx, ty;
    if (r < 1024) {
        int mat = r >> 8;
        int t = r & 255;
        K = 512; N = 512;
        src = (mat == 0 ? Wq : mat == 1 ? Wk : mat == 2 ? Wv : Wo) + (size_t)l * 262144;
        dstoff = (size_t)l * WLAYER + (size_t)mat * 262144;
        tx = t & 15; ty = t >> 4;
    } else if (r < 2048) {
        int t = r - 1024;
        K = 512; N = 2048;
        src = W1 + (size_t)l * 1048576;
        dstoff = (size_t)l * WLAYER + 1048576;
        tx = t & 63; ty = t >> 6;
    } else {
        int t = r - 2048;
        K = 2048; N = 512;
        src = W2 + (size_t)l * 1048576;
        dstoff = (size_t)l * WLAYER + 2097152;
        tx = t & 15; ty = t >> 4;
    }

    int tn = tx * 32, tk = ty * 32;
    int x = threadIdx.x, y = threadIdx.y;     // (32, 8)
    #pragma unroll
    for (int i = 0; i < 4; i++)
        tile[y + i * 8][x] = src[(size_t)(tk + y + i * 8) * N + tn + x];
    __syncthreads();
    __half* dst = Oh + dstoff;
    #pragma unroll
    for (int i = 0; i < 4; i++) {
        int nl = y + i * 8;
        dst[(size_t)(tn + nl) * K + tk + x] = __float2half_rn(tile[x][nl]);
    }
}

// ---------------- 4-stage pipelined fp16 mma GEMM with ldmatrix (R13/R15 config) ----------------
#define BKP 20
#define ARR_STRIDE (128 * BKP)
#define STAGE_BYTES (2 * ARR_STRIDE * 4)      // 20480 (A + B)
#define GEMM_SMEM4 (4 * STAGE_BYTES)          // 81920

template<int EPI, int OUTF32, int OUTF16>
__global__ __launch_bounds__(256) void gemm_pipe(
    const __half* __restrict__ Ah,
    const __half* __restrict__ Wh,
    const float* __restrict__ bias, const float* __restrict__ res,
    float* __restrict__ Cf, __half* __restrict__ Ch,
    int K, int N)
{
    uint32_t sbase = smem_u32(dyn_smem);
    int tid = threadIdx.x;
    int lane = tid & 31, wid = tid >> 5;
    int wm = wid >> 1, wn = wid & 1;
    int m0 = blockIdx.y * 128, n0 = blockIdx.x * 128;
    int g = lane >> 2, t = lane & 3;

    int lrow = tid >> 1;
    int lhalf = tid & 1;

    const __half* agh = Ah + (size_t)(m0 + lrow) * K;
    const __half* bgh = Wh + (size_t)(n0 + lrow) * K;
    uint32_t srow = sbase + (uint32_t)(lrow * BKP) * 4;

    uint32_t a_lane = sbase + (uint32_t)((wm * 32 + (lane & 15)) * BKP) * 4 + (uint32_t)(lane >> 4) * 16;
    uint32_t b_lane = sbase + (uint32_t)ARR_STRIDE * 4
                    + (uint32_t)((wn * 64 + (lane >> 4) * 8 + (lane & 7)) * BKP) * 4
                    + (uint32_t)((lane >> 3) & 1) * 16;

    const int nkb = K >> 5;

    auto issue_load = [&](int k) {
        if (k < nkb) {
            int kb = k << 5;
            uint32_t so = srow + (uint32_t)(k & 3) * STAGE_BYTES;
            #pragma unroll
            for (int p = 0; p < 2; p++) {
                int q = lhalf * 2 + p;
                int ge = kb + q * 8;
                uint32_t sb2 = so + (uint32_t)(q * 16);
                cpasync16(sb2,                  agh + ge);
                cpasync16(sb2 + ARR_STRIDE * 4, bgh + ge);
            }
        }
        cp_commit();
    };

    float c[2][8][4];
    #pragma unroll
    for (int mt = 0; mt < 2; mt++)
        #pragma unroll
        for (int nt = 0; nt < 8; nt++)
            #pragma unroll
            for (int e = 0; e < 4; e++) c[mt][nt][e] = 0.0f;

    issue_load(0);
    issue_load(1);
    issue_load(2);

    for (int k = 0; k < nkb; k++) {
        cp_wait2();
        __syncthreads();
        issue_load(k + 3);

        uint32_t so = (uint32_t)(k & 3) * STAGE_BYTES;
        uint32_t abase = a_lane + so;
        uint32_t bbase = b_lane + so;

        #pragma unroll
        for (int s = 0; s < 2; s++) {
            uint32_t acol = (uint32_t)(s * 32);
            uint32_t a0[4], a1[4];
            LDSM4(a0[0], a0[1], a0[2], a0[3], abase + acol);
            LDSM4(a1[0], a1[1], a1[2], a1[3], abase + acol + 16 * BKP * 4);
            #pragma unroll
            for (int p = 0; p < 4; p++) {
                uint32_t b0, b1, b2, b3;
                LDSM4(b0, b1, b2, b3, bbase + acol + (uint32_t)(p * 16 * BKP * 4));
                mma16816h(c[0][2 * p],     a0, b0, b1);
                mma16816h(c[1][2 * p],     a1, b0, b1);
                mma16816h(c[0][2 * p + 1], a0, b2, b3);
                mma16816h(c[1][2 * p + 1], a1, b2, b3);
            }
        }
    }

    #pragma unroll
    for (int mt = 0; mt < 2; mt++) {
        #pragma unroll
        for (int nt = 0; nt < 8; nt++) {
            int row = m0 + wm * 32 + mt * 16 + g;
            int col = n0 + wn * 64 + nt * 8 + t * 2;
            float2 v1 = make_float2(c[mt][nt][0], c[mt][nt][1]);
            float2 v2 = make_float2(c[mt][nt][2], c[mt][nt][3]);
            if (EPI == 2 || EPI == 3) {
                float2 bb = *(const float2*)(bias + col);
                v1.x += bb.x; v1.y += bb.y;
                v2.x += bb.x; v2.y += bb.y;
            }
            if (EPI == 2) {
                v1.x = fmaxf(v1.x, 0.0f); v1.y = fmaxf(v1.y, 0.0f);
                v2.x = fmaxf(v2.x, 0.0f); v2.y = fmaxf(v2.y, 0.0f);
            }
            if (EPI == 1 || EPI == 3) {
                float2 r1 = *(const float2*)(res + (size_t)row * N + col);
                float2 r2 = *(const float2*)(res + (size_t)(row + 8) * N + col);
                v1.x += r1.x; v1.y += r1.y;
                v2.x += r2.x; v2.y += r2.y;
            }
            if (OUTF32) {
                *(float2*)(Cf + (size_t)row * N + col) = v1;
                *(float2*)(Cf + (size_t)(row + 8) * N + col) = v2;
            }
            if (OUTF16) {
                *(uint32_t*)(Ch + (size_t)row * N + col) = ph2(v1.x, v1.y);
                *(uint32_t*)(Ch + (size_t)(row + 8) * N + col) = ph2(v2.x, v2.y);
            }
        }
    }
}

// ---------------- flash attention: cp.async K/V + ldmatrix(+trans) ----------------
// Rows padded to 144 B for conflict-free ldmatrix. Double-buffered K/V (2x9216 B each).
#define AROWB 144
#define OFF_Q  0
#define OFF_K  18432
#define OFF_V  36864
#define OFF_MB 55296
#define ATT_SMEM2 55808
#define NKT (SEQ / 64)

__global__ __launch_bounds__(256) void attn_mma(
    const __half* __restrict__ qkv, const int* __restrict__ mask,
    __half* __restrict__ oh)
{
    uint32_t sb = smem_u32(dyn_smem);
    uint32_t* Qs = (uint32_t*)dyn_smem;
    float* mb = (float*)(dyn_smem + OFF_MB);

    int tid = threadIdx.x;
    int lane = tid & 31, wid = tid >> 5;
    int g = lane >> 2, t = lane & 3;
    int b = blockIdx.y >> 3, h = blockIdx.y & 7;
    int q0 = blockIdx.x * 128;
    const float scale = 0.125f;
    int qrow = wid * 16;

    // ---- Q tile (fp16) -> smem, stride 144B ----
    #pragma unroll
    for (int p = 0; p < 8; p++) {
        int idx = tid + p * 256;
        int row = idx >> 4, c4 = (idx & 15) * 4;
        uint2 f = *(const uint2*)(qkv + (size_t)(b * SEQ + q0 + row) * QKVN + h * HDIM + c4);
        Qs[row * 36 + c4 / 2]     = f.x;
        Qs[row * 36 + c4 / 2 + 1] = f.y;
    }

    // ldmatrix lane bases
    uint32_t q_lane = sb + (uint32_t)((qrow + (lane & 15)) * AROWB) + (uint32_t)(lane >> 4) * 16;
    uint32_t k_lane = sb + OFF_K + (uint32_t)(((lane >> 4) * 8 + (lane & 7)) * AROWB) + (uint32_t)((lane >> 3) & 1) * 16;
    uint32_t v_lane = sb + OFF_V + (uint32_t)((lane & 15) * AROWB) + (uint32_t)(lane >> 4) * 16;

    const __half* kvbase = qkv + (size_t)(b * SEQ) * QKVN + DMODEL + h * HDIM;

    auto load_tile = [&](int kt, int st) {
        if (kt < NKT) {
            const __half* kb2 = kvbase + (size_t)(kt * 64) * QKVN;
            uint32_t ko = sb + OFF_K + (uint32_t)st * 9216;
            uint32_t vo = sb + OFF_V + (uint32_t)st * 9216;
            #pragma unroll
            for (int i = 0; i < 2; i++) {
                int idx = tid + i * 256;        // 512 chunks
                int row = idx >> 3, ch = idx & 7;
                const __half* src = kb2 + (size_t)row * QKVN + ch * 8;
                uint32_t d = (uint32_t)(row * AROWB + ch * 16);
                cpasync16(ko + d, src);
                cpasync16(vo + d, src + DMODEL);
            }
            if (tid < 64)
                mb[st * 64 + tid] = (mask[b * SEQ + kt * 64 + tid] != 0) ? 0.0f : -1e9f;
        }
        cp_commit();
    };

    float m2[2] = {-INFINITY, -INFINITY};
    float l2[2] = {0.0f, 0.0f};
    float o[8][4];
    #pragma unroll
    for (int nt = 0; nt < 8; nt++)
        #pragma unroll
        for (int e = 0; e < 4; e++) o[nt][e] = 0.0f;

    load_tile(0, 0);

    for (int kt = 0; kt < NKT; kt++) {
        int st = kt & 1;
        cp_wait0();
        __syncthreads();
        load_tile(kt + 1, st ^ 1);

        uint32_t kst = k_lane + (uint32_t)st * 9216;
        uint32_t vst = v_lane + (uint32_t)st * 9216;

        // ---- S = Q K^T ----
        float sv[8][4];
        #pragma unroll
        for (int nt = 0; nt < 8; nt++)
            #pragma unroll
            for (int e = 0; e < 4; e++) sv[nt][e] = 0.0f;

        #pragma unroll
        for (int s = 0; s < 4; s++) {
            uint32_t a[4];
            LDSM4(a[0], a[1], a[2], a[3], q_lane + (uint32_t)(s * 32));
            #pragma unroll
            for (int p = 0; p < 4; p++) {
                uint32_t b0, b1, b2, b3;
                LDSM4(b0, b1, b2, b3, kst + (uint32_t)(p * 16 * AROWB + s * 32));
                mma16816h(sv[2 * p],     a, b0, b1);
                mma16816h(sv[2 * p + 1], a, b2, b3);
            }
        }

        // ---- mask + scale + online softmax ----
        float rm0 = -INFINITY, rm1 = -INFINITY;
        #pragma unroll
        for (int nt = 0; nt < 8; nt++) {
            int col = nt * 8 + t * 2;
            float mb0 = mb[st * 64 + col], mb1 = mb[st * 64 + col + 1];
            sv[nt][0] = sv[nt][0] * scale + mb0;
            sv[nt][1] = sv[nt][1] * scale + mb1;
            sv[nt][2] = sv[nt][2] * scale + mb0;
            sv[nt][3] = sv[nt][3] * scale + mb1;
            rm0 = fmaxf(rm0, fmaxf(sv[nt][0], sv[nt][1]));
            rm1 = fmaxf(rm1, fmaxf(sv[nt][2], sv[nt][3]));
        }
        #pragma unroll
        for (int ox = 1; ox <= 2; ox <<= 1) {
            rm0 = fmaxf(rm0, __shfl_xor_sync(0xffffffffu, rm0, ox));
            rm1 = fmaxf(rm1, __shfl_xor_sync(0xffffffffu, rm1, ox));
        }
        float mn0 = fmaxf(m2[0], rm0), mn1 = fmaxf(m2[1], rm1);
        float f0 = __expf(m2[0] - mn0), f1 = __expf(m2[1] - mn1);
        m2[0] = mn0; m2[1] = mn1;

        float rs0 = 0.0f, rs1 = 0.0f;
        #pragma unroll
        for (int nt = 0; nt < 8; nt++) {
            sv[nt][0] = __expf(sv[nt][0] - mn0);
            sv[nt][1] = __expf(sv[nt][1] - mn0);
            sv[nt][2] = __expf(sv[nt][2] - mn1);
            sv[nt][3] = __expf(sv[nt][3] - mn1);
            rs0 += sv[nt][0] + sv[nt][1];
            rs1 += sv[nt][2] + sv[nt][3];
        }
        #pragma unroll
        for (int ox = 1; ox <= 2; ox <<= 1) {
            rs0 += __shfl_xor_sync(0xffffffffu, rs0, ox);
            rs1 += __shfl_xor_sync(0xffffffffu, rs1, ox);
        }
        l2[0] = l2[0] * f0 + rs0;
        l2[1] = l2[1] * f1 + rs1;
        #pragma unroll
        for (int nt = 0; nt < 8; nt++) {
            o[nt][0] *= f0; o[nt][1] *= f0;
            o[nt][2] *= f1; o[nt][3] *= f1;
        }

        // ---- O += P V  (V via ldmatrix.trans on row-major tile) ----
        #pragma unroll
        for (int s = 0; s < 4; s++) {
            uint32_t a[4];
            a[0] = ph2(sv[2 * s][0],     sv[2 * s][1]);
            a[1] = ph2(sv[2 * s][2],     sv[2 * s][3]);
            a[2] = ph2(sv[2 * s + 1][0], sv[2 * s + 1][1]);
            a[3] = ph2(sv[2 * s + 1][2], sv[2 * s + 1][3]);
            #pragma unroll
            for (int p = 0; p < 4; p++) {
                uint32_t b0, b1, b2, b3;
                LDSM4T(b0, b1, b2, b3, vst + (uint32_t)(s * 16 * AROWB + p * 32));
                mma16816h(o[2 * p],     a, b0, b1);
                mma16816h(o[2 * p + 1], a, b2, b3);
            }
        }
    }

    float i0 = 1.0f / l2[0], i1 = 1.0f / l2[1];
    #pragma unroll
    for (int nt = 0; nt < 8; nt++) {
        size_t row0 = (size_t)(b * SEQ + q0 + qrow + g) * DMODEL + h * HDIM + nt * 8 + t * 2;
        size_t row1 = row0 + 8 * DMODEL;
        *(uint32_t*)(oh + row0) = ph2(o[nt][0] * i0, o[nt][1] * i0);
        *(uint32_t*)(oh + row1) = ph2(o[nt][2] * i1, o[nt][3] * i1);
    }
}

// ---------------- host driver ----------------
extern "C" void kernel_launch(void* const* d_in, const int* in_sizes, int n_in,
                              void* d_out, int out_size)
{
    const float* x     = (const float*)d_in[0];
    const int*   mask  = (const int*)d_in[1];
    const float* Wq    = (const float*)d_in[2];
    const float* Wk    = (const float*)d_in[3];
    const float* Wv    = (const float*)d_in[4];
    const float* Wo    = (const float*)d_in[5];
    const float* ln1_g = (const float*)d_in[6];
    const float* ln1_b = (const float*)d_in[7];
    const float* ln2_g = (const float*)d_in[8];
    const float* ln2_b = (const float*)d_in[9];
    const float* W1    = (const float*)d_in[10];
    const float* b1    = (const float*)d_in[11];
    const float* W2    = (const float*)d_in[12];
    const float* b2    = (const float*)d_in[13];

    static float *px = nullptr;
    static __half *pqkvh, *plnh, *ppah, *ppfh, *pwh;
    if (!px) {
        cudaGetSymbolAddress((void**)&pqkvh, g_qkvh);
        cudaGetSymbolAddress((void**)&plnh, g_lnh);
        cudaGetSymbolAddress((void**)&ppah, g_pah);
        cudaGetSymbolAddress((void**)&ppfh, g_pfh);
        cudaGetSymbolAddress((void**)&pwh, g_wth);
        cudaFuncSetAttribute(attn_mma, cudaFuncAttributeMaxDynamicSharedMemorySize, ATT_SMEM2);
        cudaFuncSetAttribute(gemm_pipe<0,0,1>, cudaFuncAttributeMaxDynamicSharedMemorySize, GEMM_SMEM4);
        cudaFuncSetAttribute(gemm_pipe<1,1,0>, cudaFuncAttributeMaxDynamicSharedMemorySize, GEMM_SMEM4);
        cudaFuncSetAttribute(gemm_pipe<2,0,1>, cudaFuncAttributeMaxDynamicSharedMemorySize, GEMM_SMEM4);
        cudaFuncSetAttribute(gemm_pipe<3,1,0>, cudaFuncAttributeMaxDynamicSharedMemorySize, GEMM_SMEM4);
        cudaGetSymbolAddress((void**)&px, g_x);
    }

    // ---- fused weight convert+transpose (single launch) ----
    {
        dim3 blk(32, 8);
        wconv_all<<<WCONV_BLOCKS, blk>>>(Wq, Wk, Wv, Wo, W1, W2, pwh);
    }

    posenc_kernel<<<(MROWS * DMODEL + 255) / 256, 256>>>(x, px);

    dim3 gQ(QKVN / 128,   MROWS / 128);
    dim3 gD(DMODEL / 128, MROWS / 128);
    dim3 gF(DFF / 128,    MROWS / 128);
    dim3 gA(SEQ / 128, BATCH * NHEAD);

    for (int l = 0; l < NLAYERS; l++) {
        size_t base = (size_t)l * WLAYER;
        const __half *qkvh = pwh + base;
        const __half *ohp  = pwh + base + 786432;
        const __half *f1h  = pwh + base + 1048576;
        const __half *f2h  = pwh + base + 2097152;

        ln_kernel<<<MROWS, 128>>>(px, ln1_g + l * DMODEL, ln1_b + l * DMODEL, plnh);

        gemm_pipe<0,0,1><<<gQ, 256, GEMM_SMEM4>>>(plnh, qkvh, nullptr, nullptr,
                                                  nullptr, pqkvh, DMODEL, QKVN);

        attn_mma<<<gA, 256, ATT_SMEM2>>>(pqkvh, mask, ppah);

        gemm_pipe<1,1,0><<<gD, 256, GEMM_SMEM4>>>(ppah, ohp, nullptr, px,
                                                  px, nullptr, DMODEL, DMODEL);

        ln_kernel<<<MROWS, 128>>>(px, ln2_g + l * DMODEL, ln2_b + l * DMODEL, plnh);

        gemm_pipe<2,0,1><<<gF, 256, GEMM_SMEM4>>>(plnh, f1h, b1 + (size_t)l * DFF, nullptr,
                                                  nullptr, ppfh, DMODEL, DFF);

        float* outp = (l == NLAYERS - 1) ? (float*)d_out : px;
        gemm_pipe<3,1,0><<<gD, 256, GEMM_SMEM4>>>(ppfh, f2h, b2 + (size_t)l * DMODEL, px,
                                                  outp, nullptr, DFF, DMODEL);
    }
}

// round 17
// speedup vs baseline: 1.2535x; 1.0039x over previous
#include <cuda_runtime.h>
#include <cuda_fp16.h>
#include <math.h>
#include <stdint.h>

// ---------------- problem constants ----------------
#define NLAYERS 4
#define DMODEL  512
#define NHEAD   8
#define HDIM    64
#define DFF     2048
#define BATCH   8
#define SEQ     1024
#define MROWS   (BATCH*SEQ)
#define LN_EPS  1e-3f
#define QKVN    1536

#define WLAYER  3145728
#define WT_ELEMS (NLAYERS*WLAYER)

// ---------------- device scratch ----------------
__device__ float g_x   [MROWS*DMODEL];
__device__ float g_pe  [SEQ*DMODEL];
__device__ __half g_qkvh[MROWS*QKVN];
__device__ __half g_lnh[MROWS*DMODEL];
__device__ __half g_pah[MROWS*DMODEL];
__device__ __half g_pfh[MROWS*DFF];
__device__ uint4 g_wth [WT_ELEMS/8];     // weights fp16, [N][K] transposed

extern __shared__ char dyn_smem[];

// ---------------- helpers ----------------
__device__ __forceinline__ void mma16816h(float* c, const uint32_t* a, uint32_t b0, uint32_t b1) {
    asm volatile(
        "mma.sync.aligned.m16n8k16.row.col.f32.f16.f16.f32 "
        "{%0,%1,%2,%3}, {%4,%5,%6,%7}, {%8,%9}, {%0,%1,%2,%3};"
        : "+f"(c[0]), "+f"(c[1]), "+f"(c[2]), "+f"(c[3])
        : "r"(a[0]), "r"(a[1]), "r"(a[2]), "r"(a[3]), "r"(b0), "r"(b1));
}
#define LDSM4(r0, r1, r2, r3, addr) \
    asm volatile("ldmatrix.sync.aligned.m8n8.x4.shared.b16 {%0,%1,%2,%3}, [%4];" \
        : "=r"(r0), "=r"(r1), "=r"(r2), "=r"(r3) : "r"(addr))
#define LDSM4T(r0, r1, r2, r3, addr) \
    asm volatile("ldmatrix.sync.aligned.m8n8.x4.trans.shared.b16 {%0,%1,%2,%3}, [%4];" \
        : "=r"(r0), "=r"(r1), "=r"(r2), "=r"(r3) : "r"(addr))

__device__ __forceinline__ void cpasync16(uint32_t saddr, const void* gptr) {
    asm volatile("cp.async.cg.shared.global [%0], [%1], 16;" :: "r"(saddr), "l"(gptr));
}
__device__ __forceinline__ uint32_t smem_u32(const void* p) {
    uint32_t a;
    asm("{ .reg .u64 t; cvta.to.shared.u64 t, %1; cvt.u32.u64 %0, t; }" : "=r"(a) : "l"(p));
    return a;
}
__device__ __forceinline__ void cp_commit() { asm volatile("cp.async.commit_group;" ::: "memory"); }
__device__ __forceinline__ void cp_wait0()  { asm volatile("cp.async.wait_group 0;"  ::: "memory"); }
__device__ __forceinline__ void cp_wait2()  { asm volatile("cp.async.wait_group 2;"  ::: "memory"); }

__device__ __forceinline__ uint32_t ph2(float x, float y) {
    __half2 h = __floats2half2_rn(x, y);
    return *(uint32_t*)&h;
}

// ---------------- positional encoding: table build + add ----------------
__global__ void pe_build_kernel(float* __restrict__ pe) {
    int idx = blockIdx.x * 256 + threadIdx.x;
    if (idx >= SEQ * DMODEL) return;
    int d = idx & (DMODEL - 1);
    int s = idx >> 9;
    const int half = DMODEL / 2;
    float val;
    if (d < half) {
        float ang = (float)s * expf(-logf(10000.0f) * (2.0f * (float)d / (float)DMODEL));
        val = sinf(ang);
    } else {
        float j = (float)(d - half);
        float ang = (float)s * expf(-logf(10000.0f) * (2.0f * j / (float)DMODEL));
        val = cosf(ang);
    }
    pe[idx] = val;
}

__global__ void posenc_add_kernel(const float* __restrict__ x, const float* __restrict__ pe,
                                  float* __restrict__ out) {
    int idx = blockIdx.x * 256 + threadIdx.x;          // float4 index
    if (idx >= MROWS * DMODEL / 4) return;
    float4 xv = ((const float4*)x)[idx];
    float4 pv = ((const float4*)pe)[idx & (SEQ * DMODEL / 4 - 1)];
    xv.x += pv.x; xv.y += pv.y; xv.z += pv.z; xv.w += pv.w;
    ((float4*)out)[idx] = xv;
}

// ---------------- layernorm -> fp16 (2 rows per block) ----------------
__global__ void ln_kernel(const float* __restrict__ x, const float* __restrict__ gamma,
                          const float* __restrict__ beta, __half* __restrict__ oh) {
    int r = threadIdx.x >> 7;                 // 0/1
    int row = blockIdx.x * 2 + r;
    int t = threadIdx.x & 127;
    const float4* xr = (const float4*)(x + (size_t)row * DMODEL);
    float4 v = xr[t];

    __shared__ float red1[2][4];
    __shared__ float red2[2][4];

    float s = v.x + v.y + v.z + v.w;
    #pragma unroll
    for (int o = 16; o > 0; o >>= 1) s += __shfl_xor_sync(0xffffffffu, s, o);
    if ((t & 31) == 0) red1[r][t >> 5] = s;
    __syncthreads();
    float mean = (red1[r][0] + red1[r][1] + red1[r][2] + red1[r][3]) * (1.0f / DMODEL);

    float dx = v.x - mean, dy = v.y - mean, dz = v.z - mean, dw = v.w - mean;
    float s2 = dx*dx + dy*dy + dz*dz + dw*dw;
    #pragma unroll
    for (int o = 16; o > 0; o >>= 1) s2 += __shfl_xor_sync(0xffffffffu, s2, o);
    if ((t & 31) == 0) red2[r][t >> 5] = s2;
    __syncthreads();
    float var = (red2[r][0] + red2[r][1] + red2[r][2] + red2[r][3]) * (1.0f / DMODEL);
    float rs = rsqrtf(var + LN_EPS);

    float4 g4 = ((const float4*)gamma)[t];
    float4 b4 = ((const float4*)beta)[t];
    float o0 = dx * rs * g4.x + b4.x;
    float o1 = dy * rs * g4.y + b4.y;
    float o2 = dz * rs * g4.z + b4.z;
    float o3 = dw * rs * g4.w + b4.w;
    *(uint2*)(oh + (size_t)row * DMODEL + t * 4) =
        make_uint2(ph2(o0, o1), ph2(o2, o3));
}

// ---------------- fused weight convert+transpose: ALL 24 matrices, one launch ----------------
#define WCONV_BLOCKS (NLAYERS * 3072)

__global__ void wconv_all(const float* __restrict__ Wq, const float* __restrict__ Wk,
                          const float* __restrict__ Wv, const float* __restrict__ Wo,
                          const float* __restrict__ W1, const float* __restrict__ W2,
                          __half* __restrict__ Oh) {
    __shared__ float tile[32][33];
    int bid = blockIdx.x;
    int l = bid / 3072;
    int r = bid - l * 3072;

    const float* src;
    size_t dstoff;
    int K, N, tx, ty;
    if (r < 1024) {
        int mat = r >> 8;
        int t = r & 255;
        K = 512; N = 512;
        src = (mat == 0 ? Wq : mat == 1 ? Wk : mat == 2 ? Wv : Wo) + (size_t)l * 262144;
        dstoff = (size_t)l * WLAYER + (size_t)mat * 262144;
        tx = t & 15; ty = t >> 4;
    } else if (r < 2048) {
        int t = r - 1024;
        K = 512; N = 2048;
        src = W1 + (size_t)l * 1048576;
        dstoff = (size_t)l * WLAYER + 1048576;
        tx = t & 63; ty = t >> 6;
    } else {
        int t = r - 2048;
        K = 2048; N = 512;
        src = W2 + (size_t)l * 1048576;
        dstoff = (size_t)l * WLAYER + 2097152;
        tx = t & 15; ty = t >> 4;
    }

    int tn = tx * 32, tk = ty * 32;
    int x = threadIdx.x, y = threadIdx.y;     // (32, 8)
    #pragma unroll
    for (int i = 0; i < 4; i++)
        tile[y + i * 8][x] = src[(size_t)(tk + y + i * 8) * N + tn + x];
    __syncthreads();
    __half* dst = Oh + dstoff;
    #pragma unroll
    for (int i = 0; i < 4; i++) {
        int nl = y + i * 8;
        dst[(size_t)(tn + nl) * K + tk + x] = __float2half_rn(tile[x][nl]);
    }
}

// ---------------- 4-stage pipelined fp16 mma GEMM, hoisted fragment loads ----------------
#define BKP 20
#define ARR_STRIDE (128 * BKP)
#define STAGE_BYTES (2 * ARR_STRIDE * 4)      // 20480 (A + B)
#define GEMM_SMEM4 (4 * STAGE_BYTES)          // 81920

template<int EPI, int OUTF32, int OUTF16>
__global__ __launch_bounds__(256, 2) void gemm_pipe(
    const __half* __restrict__ Ah,
    const __half* __restrict__ Wh,
    const float* __restrict__ bias, const float* __restrict__ res,
    float* __restrict__ Cf, __half* __restrict__ Ch,
    int K, int N)
{
    uint32_t sbase = smem_u32(dyn_smem);
    int tid = threadIdx.x;
    int lane = tid & 31, wid = tid >> 5;
    int wm = wid >> 1, wn = wid & 1;
    int m0 = blockIdx.y * 128, n0 = blockIdx.x * 128;
    int g = lane >> 2, t = lane & 3;

    int lrow = tid >> 1;
    int lhalf = tid & 1;

    const __half* agh = Ah + (size_t)(m0 + lrow) * K;
    const __half* bgh = Wh + (size_t)(n0 + lrow) * K;
    uint32_t srow = sbase + (uint32_t)(lrow * BKP) * 4;

    uint32_t a_lane = sbase + (uint32_t)((wm * 32 + (lane & 15)) * BKP) * 4 + (uint32_t)(lane >> 4) * 16;
    uint32_t b_lane = sbase + (uint32_t)ARR_STRIDE * 4
                    + (uint32_t)((wn * 64 + (lane >> 4) * 8 + (lane & 7)) * BKP) * 4
                    + (uint32_t)((lane >> 3) & 1) * 16;

    const int nkb = K >> 5;

    auto issue_load = [&](int k) {
        if (k < nkb) {
            int kb = k << 5;
            uint32_t so = srow + (uint32_t)(k & 3) * STAGE_BYTES;
            #pragma unroll
            for (int p = 0; p < 2; p++) {
                int q = lhalf * 2 + p;
                int ge = kb + q * 8;
                uint32_t sb2 = so + (uint32_t)(q * 16);
                cpasync16(sb2,                  agh + ge);
                cpasync16(sb2 + ARR_STRIDE * 4, bgh + ge);
            }
        }
        cp_commit();
    };

    float c[2][8][4];
    #pragma unroll
    for (int mt = 0; mt < 2; mt++)
        #pragma unroll
        for (int nt = 0; nt < 8; nt++)
            #pragma unroll
            for (int e = 0; e < 4; e++) c[mt][nt][e] = 0.0f;

    issue_load(0);
    issue_load(1);
    issue_load(2);

    for (int k = 0; k < nkb; k++) {
        cp_wait2();
        __syncthreads();
        issue_load(k + 3);

        uint32_t so = (uint32_t)(k & 3) * STAGE_BYTES;
        uint32_t abase = a_lane + so;
        uint32_t bbase = b_lane + so;

        // ---- hoist ALL 12 LDSMs of this k-block into one burst ----
        uint32_t fa[2][8];       // [s][a0(4), a1(4)]
        uint32_t fb[2][16];      // [s][p*4 + r]
        #pragma unroll
        for (int s = 0; s < 2; s++) {
            uint32_t acol = (uint32_t)(s * 32);
            LDSM4(fa[s][0], fa[s][1], fa[s][2], fa[s][3], abase + acol);
            LDSM4(fa[s][4], fa[s][5], fa[s][6], fa[s][7], abase + acol + 16 * BKP * 4);
            #pragma unroll
            for (int p = 0; p < 4; p++)
                LDSM4(fb[s][p * 4], fb[s][p * 4 + 1], fb[s][p * 4 + 2], fb[s][p * 4 + 3],
                      bbase + acol + (uint32_t)(p * 16 * BKP * 4));
        }
        // ---- 32 uninterrupted MMAs ----
        #pragma unroll
        for (int s = 0; s < 2; s++) {
            #pragma unroll
            for (int p = 0; p < 4; p++) {
                mma16816h(c[0][2 * p],     &fa[s][0], fb[s][p * 4],     fb[s][p * 4 + 1]);
                mma16816h(c[1][2 * p],     &fa[s][4], fb[s][p * 4],     fb[s][p * 4 + 1]);
                mma16816h(c[0][2 * p + 1], &fa[s][0], fb[s][p * 4 + 2], fb[s][p * 4 + 3]);
                mma16816h(c[1][2 * p + 1], &fa[s][4], fb[s][p * 4 + 2], fb[s][p * 4 + 3]);
            }
        }
    }

    #pragma unroll
    for (int mt = 0; mt < 2; mt++) {
        #pragma unroll
        for (int nt = 0; nt < 8; nt++) {
            int row = m0 + wm * 32 + mt * 16 + g;
            int col = n0 + wn * 64 + nt * 8 + t * 2;
            float2 v1 = make_float2(c[mt][nt][0], c[mt][nt][1]);
            float2 v2 = make_float2(c[mt][nt][2], c[mt][nt][3]);
            if (EPI == 2 || EPI == 3) {
                float2 bb = *(const float2*)(bias + col);
                v1.x += bb.x; v1.y += bb.y;
                v2.x += bb.x; v2.y += bb.y;
            }
            if (EPI == 2) {
                v1.x = fmaxf(v1.x, 0.0f); v1.y = fmaxf(v1.y, 0.0f);
                v2.x = fmaxf(v2.x, 0.0f); v2.y = fmaxf(v2.y, 0.0f);
            }
            if (EPI == 1 || EPI == 3) {
                float2 r1 = *(const float2*)(res + (size_t)row * N + col);
                float2 r2 = *(const float2*)(res + (size_t)(row + 8) * N + col);
                v1.x += r1.x; v1.y += r1.y;
                v2.x += r2.x; v2.y += r2.y;
            }
            if (OUTF32) {
                *(float2*)(Cf + (size_t)row * N + col) = v1;
                *(float2*)(Cf + (size_t)(row + 8) * N + col) = v2;
            }
            if (OUTF16) {
                *(uint32_t*)(Ch + (size_t)row * N + col) = ph2(v1.x, v1.y);
                *(uint32_t*)(Ch + (size_t)(row + 8) * N + col) = ph2(v2.x, v2.y);
            }
        }
    }
}

// ---------------- flash attention: cp.async K/V + ldmatrix(+trans) ----------------
#define AROWB 144
#define OFF_K  18432
#define OFF_V  36864
#define OFF_MB 55296
#define ATT_SMEM2 55808
#define NKT (SEQ / 64)

__global__ __launch_bounds__(256) void attn_mma(
    const __half* __restrict__ qkv, const int* __restrict__ mask,
    __half* __restrict__ oh)
{
    uint32_t sb = smem_u32(dyn_smem);
    uint32_t* Qs = (uint32_t*)dyn_smem;
    float* mb = (float*)(dyn_smem + OFF_MB);

    int tid = threadIdx.x;
    int lane = tid & 31, wid = tid >> 5;
    int g = lane >> 2, t = lane & 3;
    int b = blockIdx.y >> 3, h = blockIdx.y & 7;
    int q0 = blockIdx.x * 128;
    const float scale = 0.125f;
    int qrow = wid * 16;

    #pragma unroll
    for (int p = 0; p < 8; p++) {
        int idx = tid + p * 256;
        int row = idx >> 4, c4 = (idx & 15) * 4;
        uint2 f = *(const uint2*)(qkv + (size_t)(b * SEQ + q0 + row) * QKVN + h * HDIM + c4);
        Qs[row * 36 + c4 / 2]     = f.x;
        Qs[row * 36 + c4 / 2 + 1] = f.y;
    }

    uint32_t q_lane = sb + (uint32_t)((qrow + (lane & 15)) * AROWB) + (uint32_t)(lane >> 4) * 16;
    uint32_t k_lane = sb + OFF_K + (uint32_t)(((lane >> 4) * 8 + (lane & 7)) * AROWB) + (uint32_t)((lane >> 3) & 1) * 16;
    uint32_t v_lane = sb + OFF_V + (uint32_t)((lane & 15) * AROWB) + (uint32_t)(lane >> 4) * 16;

    const __half* kvbase = qkv + (size_t)(b * SEQ) * QKVN + DMODEL + h * HDIM;

    auto load_tile = [&](int kt, int st) {
        if (kt < NKT) {
            const __half* kb2 = kvbase + (size_t)(kt * 64) * QKVN;
            uint32_t ko = sb + OFF_K + (uint32_t)st * 9216;
            uint32_t vo = sb + OFF_V + (uint32_t)st * 9216;
            #pragma unroll
            for (int i = 0; i < 2; i++) {
                int idx = tid + i * 256;
                int row = idx >> 3, ch = idx & 7;
                const __half* src = kb2 + (size_t)row * QKVN + ch * 8;
                uint32_t d = (uint32_t)(row * AROWB + ch * 16);
                cpasync16(ko + d, src);
                cpasync16(vo + d, src + DMODEL);
            }
            if (tid < 64)
                mb[st * 64 + tid] = (mask[b * SEQ + kt * 64 + tid] != 0) ? 0.0f : -1e9f;
        }
        cp_commit();
    };

    float m2[2] = {-INFINITY, -INFINITY};
    float l2[2] = {0.0f, 0.0f};
    float o[8][4];
    #pragma unroll
    for (int nt = 0; nt < 8; nt++)
        #pragma unroll
        for (int e = 0; e < 4; e++) o[nt][e] = 0.0f;

    load_tile(0, 0);

    for (int kt = 0; kt < NKT; kt++) {
        int st = kt & 1;
        cp_wait0();
        __syncthreads();
        load_tile(kt + 1, st ^ 1);

        uint32_t kst = k_lane + (uint32_t)st * 9216;
        uint32_t vst = v_lane + (uint32_t)st * 9216;

        float sv[8][4];
        #pragma unroll
        for (int nt = 0; nt < 8; nt++)
            #pragma unroll
            for (int e = 0; e < 4; e++) sv[nt][e] = 0.0f;

        #pragma unroll
        for (int s = 0; s < 4; s++) {
            uint32_t a[4];
            LDSM4(a[0], a[1], a[2], a[3], q_lane + (uint32_t)(s * 32));
            #pragma unroll
            for (int p = 0; p < 4; p++) {
                uint32_t b0, b1, b2, b3;
                LDSM4(b0, b1, b2, b3, kst + (uint32_t)(p * 16 * AROWB + s * 32));
                mma16816h(sv[2 * p],     a, b0, b1);
                mma16816h(sv[2 * p + 1], a, b2, b3);
            }
        }

        float rm0 = -INFINITY, rm1 = -INFINITY;
        #pragma unroll
        for (int nt = 0; nt < 8; nt++) {
            int col = nt * 8 + t * 2;
            float mb0 = mb[st * 64 + col], mb1 = mb[st * 64 + col + 1];
            sv[nt][0] = sv[nt][0] * scale + mb0;
            sv[nt][1] = sv[nt][1] * scale + mb1;
            sv[nt][2] = sv[nt][2] * scale + mb0;
            sv[nt][3] = sv[nt][3] * scale + mb1;
            rm0 = fmaxf(rm0, fmaxf(sv[nt][0], sv[nt][1]));
            rm1 = fmaxf(rm1, fmaxf(sv[nt][2], sv[nt][3]));
        }
        #pragma unroll
        for (int ox = 1; ox <= 2; ox <<= 1) {
            rm0 = fmaxf(rm0, __shfl_xor_sync(0xffffffffu, rm0, ox));
            rm1 = fmaxf(rm1, __shfl_xor_sync(0xffffffffu, rm1, ox));
        }
        float mn0 = fmaxf(m2[0], rm0), mn1 = fmaxf(m2[1], rm1);
        float f0 = __expf(m2[0] - mn0), f1 = __expf(m2[1] - mn1);
        m2[0] = mn0; m2[1] = mn1;

        float rs0 = 0.0f, rs1 = 0.0f;
        #pragma unroll
        for (int nt = 0; nt < 8; nt++) {
            sv[nt][0] = __expf(sv[nt][0] - mn0);
            sv[nt][1] = __expf(sv[nt][1] - mn0);
            sv[nt][2] = __expf(sv[nt][2] - mn1);
            sv[nt][3] = __expf(sv[nt][3] - mn1);
            rs0 += sv[nt][0] + sv[nt][1];
            rs1 += sv[nt][2] + sv[nt][3];
        }
        #pragma unroll
        for (int ox = 1; ox <= 2; ox <<= 1) {
            rs0 += __shfl_xor_sync(0xffffffffu, rs0, ox);
            rs1 += __shfl_xor_sync(0xffffffffu, rs1, ox);
        }
        l2[0] = l2[0] * f0 + rs0;
        l2[1] = l2[1] * f1 + rs1;
        #pragma unroll
        for (int nt = 0; nt < 8; nt++) {
            o[nt][0] *= f0; o[nt][1] *= f0;
            o[nt][2] *= f1; o[nt][3] *= f1;
        }

        #pragma unroll
        for (int s = 0; s < 4; s++) {
            uint32_t a[4];
            a[0] = ph2(sv[2 * s][0],     sv[2 * s][1]);
            a[1] = ph2(sv[2 * s][2],     sv[2 * s][3]);
            a[2] = ph2(sv[2 * s + 1][0], sv[2 * s + 1][1]);
            a[3] = ph2(sv[2 * s + 1][2], sv[2 * s + 1][3]);
            #pragma unroll
            for (int p = 0; p < 4; p++) {
                uint32_t b0, b1, b2, b3;
                LDSM4T(b0, b1, b2, b3, vst + (uint32_t)(s * 16 * AROWB + p * 32));
                mma16816h(o[2 * p],     a, b0, b1);
                mma16816h(o[2 * p + 1], a, b2, b3);
            }
        }
    }

    float i0 = 1.0f / l2[0], i1 = 1.0f / l2[1];
    #pragma unroll
    for (int nt = 0; nt < 8; nt++) {
        size_t row0 = (size_t)(b * SEQ + q0 + qrow + g) * DMODEL + h * HDIM + nt * 8 + t * 2;
        size_t row1 = row0 + 8 * DMODEL;
        *(uint32_t*)(oh + row0) = ph2(o[nt][0] * i0, o[nt][1] * i0);
        *(uint32_t*)(oh + row1) = ph2(o[nt][2] * i1, o[nt][3] * i1);
    }
}

// ---------------- host driver ----------------
extern "C" void kernel_launch(void* const* d_in, const int* in_sizes, int n_in,
                              void* d_out, int out_size)
{
    const float* x     = (const float*)d_in[0];
    const int*   mask  = (const int*)d_in[1];
    const float* Wq    = (const float*)d_in[2];
    const float* Wk    = (const float*)d_in[3];
    const float* Wv    = (const float*)d_in[4];
    const float* Wo    = (const float*)d_in[5];
    const float* ln1_g = (const float*)d_in[6];
    const float* ln1_b = (const float*)d_in[7];
    const float* ln2_g = (const float*)d_in[8];
    const float* ln2_b = (const float*)d_in[9];
    const float* W1    = (const float*)d_in[10];
    const float* b1    = (const float*)d_in[11];
    const float* W2    = (const float*)d_in[12];
    const float* b2    = (const float*)d_in[13];

    static float *px = nullptr, *ppe;
    static __half *pqkvh, *plnh, *ppah, *ppfh, *pwh;
    if (!px) {
        cudaGetSymbolAddress((void**)&ppe, g_pe);
        cudaGetSymbolAddress((void**)&pqkvh, g_qkvh);
        cudaGetSymbolAddress((void**)&plnh, g_lnh);
        cudaGetSymbolAddress((void**)&ppah, g_pah);
        cudaGetSymbolAddress((void**)&ppfh, g_pfh);
        cudaGetSymbolAddress((void**)&pwh, g_wth);
        cudaFuncSetAttribute(attn_mma, cudaFuncAttributeMaxDynamicSharedMemorySize, ATT_SMEM2);
        cudaFuncSetAttribute(gemm_pipe<0,0,1>, cudaFuncAttributeMaxDynamicSharedMemorySize, GEMM_SMEM4);
        cudaFuncSetAttribute(gemm_pipe<1,1,0>, cudaFuncAttributeMaxDynamicSharedMemorySize, GEMM_SMEM4);
        cudaFuncSetAttribute(gemm_pipe<2,0,1>, cudaFuncAttributeMaxDynamicSharedMemorySize, GEMM_SMEM4);
        cudaFuncSetAttribute(gemm_pipe<3,1,0>, cudaFuncAttributeMaxDynamicSharedMemorySize, GEMM_SMEM4);
        cudaGetSymbolAddress((void**)&px, g_x);
    }

    // ---- weight convert + pos-encoding table (independent) ----
    {
        dim3 blk(32, 8);
        wconv_all<<<WCONV_BLOCKS, blk>>>(Wq, Wk, Wv, Wo, W1, W2, pwh);
        pe_build_kernel<<<(SEQ * DMODEL + 255) / 256, 256>>>(ppe);
    }

    posenc_add_kernel<<<(MROWS * DMODEL / 4 + 255) / 256, 256>>>(x, ppe, px);

    dim3 gQ(QKVN / 128,   MROWS / 128);
    dim3 gD(DMODEL / 128, MROWS / 128);
    dim3 gF(DFF / 128,    MROWS / 128);
    dim3 gA(SEQ / 128, BATCH * NHEAD);

    for (int l = 0; l < NLAYERS; l++) {
        size_t base = (size_t)l * WLAYER;
        const __half *qkvh = pwh + base;
        const __half *ohp  = pwh + base + 786432;
        const __half *f1h  = pwh + base + 1048576;
        const __half *f2h  = pwh + base + 2097152;

        ln_kernel<<<MROWS / 2, 256>>>(px, ln1_g + l * DMODEL, ln1_b + l * DMODEL, plnh);

        gemm_pipe<0,0,1><<<gQ, 256, GEMM_SMEM4>>>(plnh, qkvh, nullptr, nullptr,
                                                  nullptr, pqkvh, DMODEL, QKVN);

        attn_mma<<<gA, 256, ATT_SMEM2>>>(pqkvh, mask, ppah);

        gemm_pipe<1,1,0><<<gD, 256, GEMM_SMEM4>>>(ppah, ohp, nullptr, px,
                                                  px, nullptr, DMODEL, DMODEL);

        ln_kernel<<<MROWS / 2, 256>>>(px, ln2_g + l * DMODEL, ln2_b + l * DMODEL, plnh);

        gemm_pipe<2,0,1><<<gF, 256, GEMM_SMEM4>>>(plnh, f1h, b1 + (size_t)l * DFF, nullptr,
                                                  nullptr, ppfh, DMODEL, DFF);

        float* outp = (l == NLAYERS - 1) ? (float*)d_out : px;
        gemm_pipe<3,1,0><<<gD, 256, GEMM_SMEM4>>>(ppfh, f2h, b2 + (size_t)l * DMODEL, px,
                                                  outp, nullptr, DFF, DMODEL);
    }
}